// round 6
// baseline (speedup 1.0000x reference)
#include <cuda_runtime.h>
#include <math.h>

#define FULL 0xffffffffu
constexpr int D = 64;
constexpr int MAXN = 50048;
constexpr int MAXE = 800000;

// ---- scratch (no allocations allowed) ----
__device__ float g_x[MAXN * D];
__device__ float g_s[MAXN * D];
__device__ float g_hw[MAXN * D];
__device__ float g_sw[MAXN * D];
__device__ float g_aggx[MAXN * D];
__device__ float g_aggs[MAXN * D];
__device__ float g_dinv[MAXN];
__device__ float g_stats[2 * D];
__device__ float g_pooled[128 * D];
__device__ int g_src[MAXE];
__device__ int g_dst[MAXE];
__device__ int g_batch[MAXN];
__device__ int g_is64;

// ---------------------------------------------------------------
// dtype sniffer: for int64 data, every odd 32-bit word (hi word) is 0
// (all values are small non-negative). For int32 edge data, odd words are
// uniform node ids — nonzero with overwhelming probability over 2048 samples.
__global__ void k_detect(const int* __restrict__ eraw, int totalInts) {
    __shared__ int anyNZ;
    if (threadIdx.x == 0) anyNZ = 0;
    __syncthreads();
    int limit = min(totalInts, 4096);
    for (int i = threadIdx.x * 2 + 1; i < limit; i += 512)
        if (eraw[i] != 0) anyNZ = 1;
    __syncthreads();
    if (threadIdx.x == 0) g_is64 = anyNZ ? 0 : 1;
}

__global__ void k_convert(const int* __restrict__ eraw, const int* __restrict__ braw,
                          int E, int n) {
    int i = blockIdx.x * blockDim.x + threadIdx.x;
    bool is64 = (g_is64 != 0);
    if (i < E) {
        if (is64) {
            g_src[i] = eraw[2 * i];
            g_dst[i] = eraw[2 * (E + i)];
        } else {
            g_src[i] = eraw[i];
            g_dst[i] = eraw[E + i];
        }
    }
    if (i < n) g_batch[i] = is64 ? braw[2 * i] : braw[i];
}

// ---------------------------------------------------------------
__global__ void k_zero(float* pooled, int n, int G) {
    int i = blockIdx.x * blockDim.x + threadIdx.x;
    if (i < n) g_dinv[i] = 0.f;
    if (i < 2 * D) g_stats[i] = 0.f;
    if (i < G * D) pooled[i] = 0.f;
}

__global__ void k_deg(int E, int n) {
    int e = blockIdx.x * blockDim.x + threadIdx.x;
    if (e < E) {
        int d = g_dst[e];
        if ((unsigned)d < (unsigned)n) atomicAdd(&g_dinv[d], 1.0f);
    }
}

__global__ void k_dinv(int n) {
    int i = blockIdx.x * blockDim.x + threadIdx.x;
    if (i < n) g_dinv[i] = rsqrtf(g_dinv[i] + 1.0f);  // +1 self loop
}

// ---------------------------------------------------------------
// hw = x @ W1[0:64,:] + s @ W1[64:128,:] ; sw = s @ Wg
// aggx = hw (GIN self term) ; aggs = dinv^2 * sw (GCN self-loop)
__global__ void k1_gemm(const float* __restrict__ xin, const float* __restrict__ sin,
                        const float* __restrict__ W1, const float* __restrict__ Wg, int n) {
    __shared__ float W1s[128 * 64];
    __shared__ float Wgs[64 * 64];
    int tid = threadIdx.x;
    for (int i = tid; i < 128 * 64; i += 256) W1s[i] = W1[i];
    for (int i = tid; i < 64 * 64; i += 256) Wgs[i] = Wg[i];
    __syncthreads();
    int lane = tid & 31;
    int warp = blockIdx.x * 8 + (tid >> 5);
    int r0 = warp * 4;
    if (r0 >= n) return;

    float xa[4], xb[4], sa[4], sb[4];
#pragma unroll
    for (int r = 0; r < 4; r++) {
        int row = min(r0 + r, n - 1);
        xa[r] = xin[row * 64 + lane];  xb[r] = xin[row * 64 + 32 + lane];
        sa[r] = sin[row * 64 + lane];  sb[r] = sin[row * 64 + 32 + lane];
    }
    float h0[4] = {0,0,0,0}, h1[4] = {0,0,0,0}, w0[4] = {0,0,0,0}, w1[4] = {0,0,0,0};
#pragma unroll 8
    for (int k = 0; k < 32; k++) {
        float wa = W1s[k * 64 + lane],          wa2 = W1s[k * 64 + 32 + lane];
        float wb = W1s[(64 + k) * 64 + lane],   wb2 = W1s[(64 + k) * 64 + 32 + lane];
        float wg = Wgs[k * 64 + lane],          wg2 = Wgs[k * 64 + 32 + lane];
#pragma unroll
        for (int r = 0; r < 4; r++) {
            float xv = __shfl_sync(FULL, xa[r], k);
            float sv = __shfl_sync(FULL, sa[r], k);
            h0[r] += xv * wa;  h0[r] += sv * wb;
            h1[r] += xv * wa2; h1[r] += sv * wb2;
            w0[r] += sv * wg;  w1[r] += sv * wg2;
        }
    }
#pragma unroll 8
    for (int k = 0; k < 32; k++) {
        int kk = k + 32;
        float wa = W1s[kk * 64 + lane],          wa2 = W1s[kk * 64 + 32 + lane];
        float wb = W1s[(64 + kk) * 64 + lane],   wb2 = W1s[(64 + kk) * 64 + 32 + lane];
        float wg = Wgs[kk * 64 + lane],          wg2 = Wgs[kk * 64 + 32 + lane];
#pragma unroll
        for (int r = 0; r < 4; r++) {
            float xv = __shfl_sync(FULL, xb[r], k);
            float sv = __shfl_sync(FULL, sb[r], k);
            h0[r] += xv * wa;  h0[r] += sv * wb;
            h1[r] += xv * wa2; h1[r] += sv * wb2;
            w0[r] += sv * wg;  w1[r] += sv * wg2;
        }
    }
#pragma unroll
    for (int r = 0; r < 4; r++) {
        int row = r0 + r;
        if (row >= n) break;
        float dv = g_dinv[row], d2 = dv * dv;
        g_hw[row * 64 + lane] = h0[r];        g_hw[row * 64 + 32 + lane] = h1[r];
        g_sw[row * 64 + lane] = w0[r];        g_sw[row * 64 + 32 + lane] = w1[r];
        g_aggx[row * 64 + lane] = h0[r];      g_aggx[row * 64 + 32 + lane] = h1[r];
        g_aggs[row * 64 + lane] = d2 * w0[r]; g_aggs[row * 64 + 32 + lane] = d2 * w1[r];
    }
}

// ---------------------------------------------------------------
__device__ __forceinline__ void red4(float* p, float a, float b, float c, float d) {
    asm volatile("red.global.add.v4.f32 [%0], {%1,%2,%3,%4};"
                 :: "l"(p), "f"(a), "f"(b), "f"(c), "f"(d) : "memory");
}

// fused GIN + GCN edge scatter: 8 threads per edge
__global__ void k2_scatter(int E, int n) {
    int t = blockIdx.x * blockDim.x + threadIdx.x;
    int e = t >> 3;
    if (e >= E) return;
    int g = t & 7;
    int si = g_src[e];
    int di = g_dst[e];
    if ((unsigned)si >= (unsigned)n || (unsigned)di >= (unsigned)n) return;
    float nrm = g_dinv[si] * g_dinv[di];
    const float4* hs = (const float4*)(g_hw + si * 64);
    const float4* ss = (const float4*)(g_sw + si * 64);
    float4 a = hs[g], b = hs[g + 8];
    float4 c = ss[g], d4 = ss[g + 8];
    float* px = g_aggx + di * 64 + g * 4;
    float* ps = g_aggs + di * 64 + g * 4;
    red4(px,      a.x, a.y, a.z, a.w);
    red4(px + 32, b.x, b.y, b.z, b.w);
    red4(ps,      nrm * c.x, nrm * c.y, nrm * c.z, nrm * c.w);
    red4(ps + 32, nrm * d4.x, nrm * d4.y, nrm * d4.z, nrm * d4.w);
}

// ---------------------------------------------------------------
// x = leaky(aggx) @ W2 ; s = tanh(aggs + bg) ; optional BN stats
__global__ void k3_mlp(const float* __restrict__ W2, const float* __restrict__ bg,
                       int n, int doStats) {
    __shared__ float Ws[64 * 64];
    __shared__ float shst[128];
    int tid = threadIdx.x;
    for (int i = tid; i < 64 * 64; i += 256) Ws[i] = W2[i];
    if (tid < 128) shst[tid] = 0.f;
    __syncthreads();
    int lane = tid & 31;
    int warp = blockIdx.x * 8 + (tid >> 5);
    int r0 = warp * 4;
    bool active = (r0 < n);
    float sum0 = 0.f, sum1 = 0.f, sq0 = 0.f, sq1 = 0.f;
    if (active) {
        float a0[4], a1[4];
#pragma unroll
        for (int r = 0; r < 4; r++) {
            int row = min(r0 + r, n - 1);
            float v0 = g_aggx[row * 64 + lane], v1 = g_aggx[row * 64 + 32 + lane];
            a0[r] = v0 > 0.f ? v0 : 0.01f * v0;
            a1[r] = v1 > 0.f ? v1 : 0.01f * v1;
        }
        float o0[4] = {0,0,0,0}, o1[4] = {0,0,0,0};
#pragma unroll 8
        for (int k = 0; k < 32; k++) {
            float w = Ws[k * 64 + lane], w2 = Ws[k * 64 + 32 + lane];
#pragma unroll
            for (int r = 0; r < 4; r++) {
                float xv = __shfl_sync(FULL, a0[r], k);
                o0[r] += xv * w; o1[r] += xv * w2;
            }
        }
#pragma unroll 8
        for (int k = 0; k < 32; k++) {
            int kk = k + 32;
            float w = Ws[kk * 64 + lane], w2 = Ws[kk * 64 + 32 + lane];
#pragma unroll
            for (int r = 0; r < 4; r++) {
                float xv = __shfl_sync(FULL, a1[r], k);
                o0[r] += xv * w; o1[r] += xv * w2;
            }
        }
        float b0 = bg[lane], b1 = bg[32 + lane];
#pragma unroll
        for (int r = 0; r < 4; r++) {
            int row = r0 + r;
            if (row >= n) break;
            g_x[row * 64 + lane] = o0[r]; g_x[row * 64 + 32 + lane] = o1[r];
            g_s[row * 64 + lane]      = tanhf(g_aggs[row * 64 + lane] + b0);
            g_s[row * 64 + 32 + lane] = tanhf(g_aggs[row * 64 + 32 + lane] + b1);
            sum0 += o0[r]; sq0 += o0[r] * o0[r];
            sum1 += o1[r]; sq1 += o1[r] * o1[r];
        }
    }
    if (doStats) {
        atomicAdd(&shst[lane], sum0);
        atomicAdd(&shst[32 + lane], sum1);
        atomicAdd(&shst[64 + lane], sq0);
        atomicAdd(&shst[96 + lane], sq1);
        __syncthreads();
        if (tid < 128) atomicAdd(&g_stats[tid], shst[tid]);
    }
}

__global__ void k_bn(int n) {
    int c = threadIdx.x;  // 64 threads
    float mean = g_stats[c] / (float)n;
    float var = g_stats[64 + c] / (float)n - mean * mean;
    g_stats[c] = mean;
    g_stats[64 + c] = rsqrtf(var + 1e-4f);
}

// ---------------------------------------------------------------
__global__ void k_final(const float* __restrict__ gamma, const float* __restrict__ beta,
                        const float* __restrict__ Wh, const float* __restrict__ bh,
                        float* __restrict__ pooled, float* __restrict__ xl_out,
                        int n, int G) {
    __shared__ float Ws[128 * 64];
    int tid = threadIdx.x;
    for (int i = tid; i < 128 * 64; i += 256) Ws[i] = Wh[i];
    __syncthreads();
    int lane = tid & 31;
    int warp = blockIdx.x * 8 + (tid >> 5);
    int r0 = warp * 4;
    if (r0 >= n) return;
    float m0 = g_stats[lane],      m1 = g_stats[32 + lane];
    float i0 = g_stats[64 + lane], i1 = g_stats[96 + lane];
    float ga0 = gamma[lane], ga1 = gamma[32 + lane];
    float be0 = beta[lane],  be1 = beta[32 + lane];
    float xl0[4], xl1[4], sv0[4], sv1[4];
    int bidx[4];
#pragma unroll
    for (int r = 0; r < 4; r++) {
        int row = min(r0 + r, n - 1);
        xl0[r] = ga0 * (g_x[row * 64 + lane] - m0) * i0 + be0;
        xl1[r] = ga1 * (g_x[row * 64 + 32 + lane] - m1) * i1 + be1;
        sv0[r] = g_s[row * 64 + lane];
        sv1[r] = g_s[row * 64 + 32 + lane];
        int b = g_batch[row];
        bidx[r] = ((unsigned)b < (unsigned)G) ? b : 0;
    }
    float bh0 = bh[lane], bh1 = bh[32 + lane];
    float o0[4], o1[4];
#pragma unroll
    for (int r = 0; r < 4; r++) { o0[r] = bh0; o1[r] = bh1; }
#pragma unroll 8
    for (int k = 0; k < 32; k++) {
        float w = Ws[k * 64 + lane], w2 = Ws[k * 64 + 32 + lane];
#pragma unroll
        for (int r = 0; r < 4; r++) { float v = __shfl_sync(FULL, xl0[r], k); o0[r] += v * w; o1[r] += v * w2; }
    }
#pragma unroll 8
    for (int k = 0; k < 32; k++) {
        int kk = 32 + k;
        float w = Ws[kk * 64 + lane], w2 = Ws[kk * 64 + 32 + lane];
#pragma unroll
        for (int r = 0; r < 4; r++) { float v = __shfl_sync(FULL, xl1[r], k); o0[r] += v * w; o1[r] += v * w2; }
    }
#pragma unroll 8
    for (int k = 0; k < 32; k++) {
        int kk = 64 + k;
        float w = Ws[kk * 64 + lane], w2 = Ws[kk * 64 + 32 + lane];
#pragma unroll
        for (int r = 0; r < 4; r++) { float v = __shfl_sync(FULL, sv0[r], k); o0[r] += v * w; o1[r] += v * w2; }
    }
#pragma unroll 8
    for (int k = 0; k < 32; k++) {
        int kk = 96 + k;
        float w = Ws[kk * 64 + lane], w2 = Ws[kk * 64 + 32 + lane];
#pragma unroll
        for (int r = 0; r < 4; r++) { float v = __shfl_sync(FULL, sv1[r], k); o0[r] += v * w; o1[r] += v * w2; }
    }
    if (xl_out) {
#pragma unroll
        for (int r = 0; r < 4; r++) {
            int row = r0 + r;
            if (row >= n) break;
            xl_out[row * 64 + lane] = xl0[r];
            xl_out[row * 64 + 32 + lane] = xl1[r];
        }
    }
    int nvalid = min(n - r0, 4);
    if (nvalid == 4 && bidx[0] == bidx[1] && bidx[1] == bidx[2] && bidx[2] == bidx[3]) {
        float p0 = o0[0] + o0[1] + o0[2] + o0[3];
        float p1 = o1[0] + o1[1] + o1[2] + o1[3];
        atomicAdd(&pooled[bidx[0] * 64 + lane], p0);
        atomicAdd(&pooled[bidx[0] * 64 + 32 + lane], p1);
    } else {
        for (int r = 0; r < nvalid; r++) {
            atomicAdd(&pooled[bidx[r] * 64 + lane], o0[r]);
            atomicAdd(&pooled[bidx[r] * 64 + 32 + lane], o1[r]);
        }
    }
}

// ---------------------------------------------------------------
extern "C" void kernel_launch(void* const* d_in, const int* in_sizes, int n_in,
                              void* d_out, int out_size) {
    // dict-order inputs (x, s equal sizes at [0],[1] confirmed)
    int ix, is_, iW1, iW2, iGa, iBe, iWg, iBg, iWh, iBh, iEi, iBa;
    if (n_in >= 2 && in_sizes[0] == in_sizes[1]) {
        ix = 0; is_ = 1; iW1 = 2; iW2 = 3; iGa = 4; iBe = 5;
        iWg = 6; iBg = 7; iWh = 8; iBh = 9; iEi = 10; iBa = 11;
    } else {
        iW1 = 0; iW2 = 1; iWg = 2; iWh = 3; iBa = 4; iBe = 5;
        iBg = 6; iBh = 7; iEi = 8; iGa = 9; is_ = 10; ix = 11;
    }

    const float* x     = (const float*)d_in[ix];
    const float* s     = (const float*)d_in[is_];
    const float* W1    = (const float*)d_in[iW1];
    const float* W2    = (const float*)d_in[iW2];
    const float* gamma = (const float*)d_in[iGa];
    const float* beta  = (const float*)d_in[iBe];
    const float* Wg    = (const float*)d_in[iWg];
    const float* bg    = (const float*)d_in[iBg];
    const float* Wh    = (const float*)d_in[iWh];
    const float* bh    = (const float*)d_in[iBh];
    const int* eraw    = (const int*)d_in[iEi];   // int32 OR int64 (auto-detected)
    const int* braw    = (const int*)d_in[iBa];
    float* out = (float*)d_out;

    int n = in_sizes[ix] / 64;
    int E = in_sizes[iEi] / 2;
    if (n > MAXN) n = MAXN;
    if (E > MAXE) E = MAXE;

    // ---- output layout resolution ----
    float* pooledPtr;
    float* xlocalPtr;
    int G;
    float* gpool;
    cudaGetSymbolAddress((void**)&gpool, g_pooled);
    if (out_size > n * 64) {            // concat(pooled, x_local)
        G = out_size / 64 - n;
        pooledPtr = out;
        xlocalPtr = out + (long)G * 64;
    } else if (out_size == n * 64) {    // x_local only
        G = 64;
        pooledPtr = gpool;
        xlocalPtr = out;
    } else {                            // pooled only
        G = out_size / 64;
        pooledPtr = out;
        xlocalPtr = nullptr;
    }
    if (G > 128) G = 128;
    if (G < 1) G = 1;

    int gemmBlocks = (((n + 3) / 4) + 7) / 8;
    int cvtBlocks = ((E > n ? E : n) + 255) / 256;

    float *gx, *gs;
    cudaGetSymbolAddress((void**)&gx, g_x);
    cudaGetSymbolAddress((void**)&gs, g_s);

    k_detect<<<1, 256>>>(eraw, 2 * E);
    k_convert<<<cvtBlocks, 256>>>(eraw, braw, E, n);
    k_zero<<<(n + 255) / 256, 256>>>(pooledPtr, n, G);
    k_deg<<<(E + 255) / 256, 256>>>(E, n);
    k_dinv<<<(n + 255) / 256, 256>>>(n);

    const float* xi = x;
    const float* si = s;
    for (int i = 0; i < 3; i++) {
        k1_gemm<<<gemmBlocks, 256>>>(xi, si, W1 + i * 128 * 64, Wg + i * 64 * 64, n);
        k2_scatter<<<(E * 8 + 255) / 256, 256>>>(E, n);
        k3_mlp<<<gemmBlocks, 256>>>(W2 + i * 64 * 64, bg + i * 64, n, (i == 2) ? 1 : 0);
        xi = gx; si = gs;
    }
    k_bn<<<1, 64>>>(n);
    k_final<<<gemmBlocks, 256>>>(gamma + 2 * 64, beta + 2 * 64, Wh, bh,
                                 pooledPtr, xlocalPtr, n, G);
}

// round 9
// speedup vs baseline: 1.1845x; 1.1845x over previous
#include <cuda_runtime.h>
#include <math.h>

#define FULL 0xffffffffu
constexpr int D = 64;
constexpr int MAXN = 50048;
constexpr int MAXE = 800000;

// ---- scratch (no allocations allowed) ----
__device__ float g_x[MAXN * D];
__device__ float g_s[MAXN * D];
__device__ float g_hw[MAXN * D];
__device__ float g_sw[MAXN * D];
__device__ float g_aggx[MAXN * D];
__device__ float g_aggs[MAXN * D];
__device__ float g_dinv[MAXN];
__device__ float g_stats[2 * D];
__device__ float g_pooled[128 * D];
__device__ float g_M[2 * D * D];      // W2_l @ W1_{l+1}[0:64,:]
__device__ int g_src[MAXE];
__device__ int g_dst[MAXE];
__device__ int g_csr[MAXE];
__device__ int g_batch[MAXN];
__device__ int g_degi[MAXN];
__device__ int g_rowstart[MAXN + 1];
__device__ int g_cursor[MAXN];
__device__ int g_is64;

// ---------------------------------------------------------------
// dtype sniffer: int64 data has all odd 32-bit (hi) words zero.
__global__ void k_detect(const int* __restrict__ eraw, int totalInts) {
    __shared__ int anyNZ;
    if (threadIdx.x == 0) anyNZ = 0;
    __syncthreads();
    int limit = min(totalInts, 4096);
    for (int i = threadIdx.x * 2 + 1; i < limit; i += 512)
        if (eraw[i] != 0) anyNZ = 1;
    __syncthreads();
    if (threadIdx.x == 0) g_is64 = anyNZ ? 0 : 1;
}

__global__ void k_convert(const int* __restrict__ eraw, const int* __restrict__ braw,
                          int E, int n) {
    int i = blockIdx.x * blockDim.x + threadIdx.x;
    bool is64 = (g_is64 != 0);
    if (i < E) {
        int sv = is64 ? eraw[2 * i] : eraw[i];
        int dv = is64 ? eraw[2 * (E + i)] : eraw[E + i];
        if ((unsigned)sv >= (unsigned)n) sv = 0;
        if ((unsigned)dv >= (unsigned)n) dv = 0;
        g_src[i] = sv;
        g_dst[i] = dv;
    }
    if (i < n) {
        int b = is64 ? braw[2 * i] : braw[i];
        g_batch[i] = b;
    }
}

// ---------------------------------------------------------------
__global__ void k_zero(float* pooled, int n, int G) {
    int i = blockIdx.x * blockDim.x + threadIdx.x;
    if (i < n) g_degi[i] = 0;
    if (i < 2 * D) g_stats[i] = 0.f;
    if (i < G * D) pooled[i] = 0.f;
}

__global__ void k_deg(int E) {
    int e = blockIdx.x * blockDim.x + threadIdx.x;
    if (e < E) atomicAdd(&g_degi[g_dst[e]], 1);
}

// one-block scan: rowstart (exclusive), cursor copy, dinv
__global__ void k_scan(int n) {
    __shared__ int ssum[1024];
    int t = threadIdx.x;
    int chunk = (n + 1023) / 1024;
    int b0 = t * chunk;
    int hi = min(b0 + chunk, n);
    int local = 0;
    for (int i = b0; i < hi; i++) local += g_degi[i];
    ssum[t] = local;
    __syncthreads();
    for (int off = 1; off < 1024; off <<= 1) {
        int v = (t >= off) ? ssum[t - off] : 0;
        __syncthreads();
        ssum[t] += v;
        __syncthreads();
    }
    int run = (t == 0) ? 0 : ssum[t - 1];
    for (int i = b0; i < hi; i++) {
        g_rowstart[i] = run;
        g_cursor[i] = run;
        int d = g_degi[i];
        g_dinv[i] = rsqrtf((float)d + 1.0f);
        run += d;
    }
    if (t == 0) g_rowstart[n] = ssum[1023];
}

__global__ void k_fill(int E) {
    int e = blockIdx.x * blockDim.x + threadIdx.x;
    if (e < E) {
        int pos = atomicAdd(&g_cursor[g_dst[e]], 1);
        g_csr[pos] = g_src[e];
    }
}

// ---------------------------------------------------------------
// M[l] = W2_l @ W1_{l+1}[0:64,:]
__global__ void k_precompute(const float* __restrict__ W1, const float* __restrict__ W2) {
    int b = blockIdx.x;           // 128 blocks: l = b>>6, k = b&63
    int l = b >> 6, k = b & 63;
    int c = threadIdx.x;          // 64 threads
    const float* W2l = W2 + l * 4096;
    const float* W1a = W1 + (l + 1) * 8192;
    float acc = 0.f;
#pragma unroll 16
    for (int j = 0; j < 64; j++) acc = fmaf(W2l[k * 64 + j], W1a[j * 64 + c], acc);
    g_M[l * 4096 + k * 64 + c] = acc;
}

// ---------------------------------------------------------------
// Layer-0 GEMM: hw = x@W1a + s@W1b ; sw = s@Wg.  Writes hw,sw only.
__global__ void k1_gemm(const float* __restrict__ xin, const float* __restrict__ sin,
                        const float* __restrict__ W1, const float* __restrict__ Wg, int n) {
    __shared__ float W1s[128 * 64];
    __shared__ float Wgs[64 * 64];
    int tid = threadIdx.x;
    for (int i = tid; i < 128 * 64; i += 256) W1s[i] = W1[i];
    for (int i = tid; i < 64 * 64; i += 256) Wgs[i] = Wg[i];
    __syncthreads();
    int lane = tid & 31;
    int warp = blockIdx.x * 8 + (tid >> 5);
    int r0 = warp * 4;
    if (r0 >= n) return;

    float xa[4], xb[4], sa[4], sb[4];
#pragma unroll
    for (int r = 0; r < 4; r++) {
        int row = min(r0 + r, n - 1);
        xa[r] = xin[row * 64 + lane];  xb[r] = xin[row * 64 + 32 + lane];
        sa[r] = sin[row * 64 + lane];  sb[r] = sin[row * 64 + 32 + lane];
    }
    float h0[4] = {0,0,0,0}, h1[4] = {0,0,0,0}, w0[4] = {0,0,0,0}, w1[4] = {0,0,0,0};
#pragma unroll 8
    for (int k = 0; k < 32; k++) {
        float wa = W1s[k * 64 + lane],          wa2 = W1s[k * 64 + 32 + lane];
        float wb = W1s[(64 + k) * 64 + lane],   wb2 = W1s[(64 + k) * 64 + 32 + lane];
        float wg = Wgs[k * 64 + lane],          wg2 = Wgs[k * 64 + 32 + lane];
#pragma unroll
        for (int r = 0; r < 4; r++) {
            float xv = __shfl_sync(FULL, xa[r], k);
            float sv = __shfl_sync(FULL, sa[r], k);
            h0[r] += xv * wa;  h0[r] += sv * wb;
            h1[r] += xv * wa2; h1[r] += sv * wb2;
            w0[r] += sv * wg;  w1[r] += sv * wg2;
        }
    }
#pragma unroll 8
    for (int k = 0; k < 32; k++) {
        int kk = k + 32;
        float wa = W1s[kk * 64 + lane],          wa2 = W1s[kk * 64 + 32 + lane];
        float wb = W1s[(64 + kk) * 64 + lane],   wb2 = W1s[(64 + kk) * 64 + 32 + lane];
        float wg = Wgs[kk * 64 + lane],          wg2 = Wgs[kk * 64 + 32 + lane];
#pragma unroll
        for (int r = 0; r < 4; r++) {
            float xv = __shfl_sync(FULL, xb[r], k);
            float sv = __shfl_sync(FULL, sb[r], k);
            h0[r] += xv * wa;  h0[r] += sv * wb;
            h1[r] += xv * wa2; h1[r] += sv * wb2;
            w0[r] += sv * wg;  w1[r] += sv * wg2;
        }
    }
#pragma unroll
    for (int r = 0; r < 4; r++) {
        int row = r0 + r;
        if (row >= n) break;
        g_hw[row * 64 + lane] = h0[r]; g_hw[row * 64 + 32 + lane] = h1[r];
        g_sw[row * 64 + lane] = w0[r]; g_sw[row * 64 + 32 + lane] = w1[r];
    }
}

// ---------------------------------------------------------------
// Fused layer GEMM (layers 1,2): a = leaky(aggx), t = tanh(aggs + bg_prev)
// hw = a@M + t@W1b ; sw = t@Wg.  Writes hw,sw only.
__global__ void k1_fused(const float* __restrict__ M, const float* __restrict__ W1b,
                         const float* __restrict__ Wg, const float* __restrict__ bgp, int n) {
    __shared__ float Ms[64 * 64];
    __shared__ float Bs[64 * 64];
    __shared__ float Gs[64 * 64];
    int tid = threadIdx.x;
    for (int i = tid; i < 64 * 64; i += 256) { Ms[i] = M[i]; Bs[i] = W1b[i]; Gs[i] = Wg[i]; }
    __syncthreads();
    int lane = tid & 31;
    int warp = blockIdx.x * 8 + (tid >> 5);
    int r0 = warp * 4;
    if (r0 >= n) return;

    float b0v = bgp[lane], b1v = bgp[32 + lane];
    float aa[4], ab[4], ta[4], tb[4];
#pragma unroll
    for (int r = 0; r < 4; r++) {
        int row = min(r0 + r, n - 1);
        float v0 = g_aggx[row * 64 + lane], v1 = g_aggx[row * 64 + 32 + lane];
        aa[r] = v0 > 0.f ? v0 : 0.01f * v0;
        ab[r] = v1 > 0.f ? v1 : 0.01f * v1;
        ta[r] = tanhf(g_aggs[row * 64 + lane] + b0v);
        tb[r] = tanhf(g_aggs[row * 64 + 32 + lane] + b1v);
    }
    float h0[4] = {0,0,0,0}, h1[4] = {0,0,0,0}, w0[4] = {0,0,0,0}, w1[4] = {0,0,0,0};
#pragma unroll 8
    for (int k = 0; k < 32; k++) {
        float wa = Ms[k * 64 + lane], wa2 = Ms[k * 64 + 32 + lane];
        float wb = Bs[k * 64 + lane], wb2 = Bs[k * 64 + 32 + lane];
        float wg = Gs[k * 64 + lane], wg2 = Gs[k * 64 + 32 + lane];
#pragma unroll
        for (int r = 0; r < 4; r++) {
            float av = __shfl_sync(FULL, aa[r], k);
            float tv = __shfl_sync(FULL, ta[r], k);
            h0[r] += av * wa;  h0[r] += tv * wb;
            h1[r] += av * wa2; h1[r] += tv * wb2;
            w0[r] += tv * wg;  w1[r] += tv * wg2;
        }
    }
#pragma unroll 8
    for (int k = 0; k < 32; k++) {
        int kk = k + 32;
        float wa = Ms[kk * 64 + lane], wa2 = Ms[kk * 64 + 32 + lane];
        float wb = Bs[kk * 64 + lane], wb2 = Bs[kk * 64 + 32 + lane];
        float wg = Gs[kk * 64 + lane], wg2 = Gs[kk * 64 + 32 + lane];
#pragma unroll
        for (int r = 0; r < 4; r++) {
            float av = __shfl_sync(FULL, ab[r], k);
            float tv = __shfl_sync(FULL, tb[r], k);
            h0[r] += av * wa;  h0[r] += tv * wb;
            h1[r] += av * wa2; h1[r] += tv * wb2;
            w0[r] += tv * wg;  w1[r] += tv * wg2;
        }
    }
#pragma unroll
    for (int r = 0; r < 4; r++) {
        int row = r0 + r;
        if (row >= n) break;
        g_hw[row * 64 + lane] = h0[r]; g_hw[row * 64 + 32 + lane] = h1[r];
        g_sw[row * 64 + lane] = w0[r]; g_sw[row * 64 + 32 + lane] = w1[r];
    }
}

// ---------------------------------------------------------------
// CSR gather: warp per dst node. aggx = hw[d] + sum hw[s];
// aggs = dinv[d]^2*sw[d] + sum nrm*sw[s]
__global__ void k_gather(int n) {
    int warp = blockIdx.x * 8 + (threadIdx.x >> 5);
    if (warp >= n) return;
    int lane = threadIdx.x & 31;
    int di = warp;
    int beg = g_rowstart[di], end = g_rowstart[di + 1];
    float dv = g_dinv[di];
    const float2* hp = (const float2*)g_hw;
    const float2* wp = (const float2*)g_sw;
    float2 h = hp[di * 32 + lane];
    float2 w = wp[di * 32 + lane];
    float ax0 = h.x, ax1 = h.y;
    float as0 = dv * dv * w.x, as1 = dv * dv * w.y;
#pragma unroll 4
    for (int j = beg; j < end; j++) {
        int sid = g_csr[j];
        float nrm = dv * g_dinv[sid];
        float2 hh = hp[sid * 32 + lane];
        float2 ww = wp[sid * 32 + lane];
        ax0 += hh.x; ax1 += hh.y;
        as0 += nrm * ww.x; as1 += nrm * ww.y;
    }
    ((float2*)g_aggx)[di * 32 + lane] = make_float2(ax0, ax1);
    ((float2*)g_aggs)[di * 32 + lane] = make_float2(as0, as1);
}

// ---------------------------------------------------------------
// Layer-2 tail: x3 = leaky(aggx)@W2 ; s3 = tanh(aggs+bg) ; BN stats
__global__ void k3_mlp(const float* __restrict__ W2, const float* __restrict__ bg, int n) {
    __shared__ float Ws[64 * 64];
    __shared__ float shst[128];
    int tid = threadIdx.x;
    for (int i = tid; i < 64 * 64; i += 256) Ws[i] = W2[i];
    if (tid < 128) shst[tid] = 0.f;
    __syncthreads();
    int lane = tid & 31;
    int warp = blockIdx.x * 8 + (tid >> 5);
    int r0 = warp * 4;
    bool active = (r0 < n);
    float sum0 = 0.f, sum1 = 0.f, sq0 = 0.f, sq1 = 0.f;
    if (active) {
        float a0[4], a1[4];
#pragma unroll
        for (int r = 0; r < 4; r++) {
            int row = min(r0 + r, n - 1);
            float v0 = g_aggx[row * 64 + lane], v1 = g_aggx[row * 64 + 32 + lane];
            a0[r] = v0 > 0.f ? v0 : 0.01f * v0;
            a1[r] = v1 > 0.f ? v1 : 0.01f * v1;
        }
        float o0[4] = {0,0,0,0}, o1[4] = {0,0,0,0};
#pragma unroll 8
        for (int k = 0; k < 32; k++) {
            float w = Ws[k * 64 + lane], w2 = Ws[k * 64 + 32 + lane];
#pragma unroll
            for (int r = 0; r < 4; r++) {
                float xv = __shfl_sync(FULL, a0[r], k);
                o0[r] += xv * w; o1[r] += xv * w2;
            }
        }
#pragma unroll 8
        for (int k = 0; k < 32; k++) {
            int kk = k + 32;
            float w = Ws[kk * 64 + lane], w2 = Ws[kk * 64 + 32 + lane];
#pragma unroll
            for (int r = 0; r < 4; r++) {
                float xv = __shfl_sync(FULL, a1[r], k);
                o0[r] += xv * w; o1[r] += xv * w2;
            }
        }
        float b0 = bg[lane], b1 = bg[32 + lane];
#pragma unroll
        for (int r = 0; r < 4; r++) {
            int row = r0 + r;
            if (row >= n) break;
            g_x[row * 64 + lane] = o0[r]; g_x[row * 64 + 32 + lane] = o1[r];
            g_s[row * 64 + lane]      = tanhf(g_aggs[row * 64 + lane] + b0);
            g_s[row * 64 + 32 + lane] = tanhf(g_aggs[row * 64 + 32 + lane] + b1);
            sum0 += o0[r]; sq0 += o0[r] * o0[r];
            sum1 += o1[r]; sq1 += o1[r] * o1[r];
        }
    }
    atomicAdd(&shst[lane], sum0);
    atomicAdd(&shst[32 + lane], sum1);
    atomicAdd(&shst[64 + lane], sq0);
    atomicAdd(&shst[96 + lane], sq1);
    __syncthreads();
    if (tid < 128) atomicAdd(&g_stats[tid], shst[tid]);
}

__global__ void k_bn(int n) {
    int c = threadIdx.x;  // 64 threads
    float mean = g_stats[c] / (float)n;
    float var = g_stats[64 + c] / (float)n - mean * mean;
    g_stats[c] = mean;
    g_stats[64 + c] = rsqrtf(var + 1e-4f);
}

// ---------------------------------------------------------------
__global__ void k_final(const float* __restrict__ gamma, const float* __restrict__ beta,
                        const float* __restrict__ Wh, const float* __restrict__ bh,
                        float* __restrict__ pooled, float* __restrict__ xl_out,
                        int n, int G) {
    __shared__ float Ws[128 * 64];
    int tid = threadIdx.x;
    for (int i = tid; i < 128 * 64; i += 256) Ws[i] = Wh[i];
    __syncthreads();
    int lane = tid & 31;
    int warp = blockIdx.x * 8 + (tid >> 5);
    int r0 = warp * 4;
    if (r0 >= n) return;
    float m0 = g_stats[lane],      m1 = g_stats[32 + lane];
    float i0 = g_stats[64 + lane], i1 = g_stats[96 + lane];
    float ga0 = gamma[lane], ga1 = gamma[32 + lane];
    float be0 = beta[lane],  be1 = beta[32 + lane];
    float xl0[4], xl1[4], sv0[4], sv1[4];
    int bidx[4];
#pragma unroll
    for (int r = 0; r < 4; r++) {
        int row = min(r0 + r, n - 1);
        xl0[r] = ga0 * (g_x[row * 64 + lane] - m0) * i0 + be0;
        xl1[r] = ga1 * (g_x[row * 64 + 32 + lane] - m1) * i1 + be1;
        sv0[r] = g_s[row * 64 + lane];
        sv1[r] = g_s[row * 64 + 32 + lane];
        int b = g_batch[row];
        bidx[r] = ((unsigned)b < (unsigned)G) ? b : 0;
    }
    float bh0 = bh[lane], bh1 = bh[32 + lane];
    float o0[4], o1[4];
#pragma unroll
    for (int r = 0; r < 4; r++) { o0[r] = bh0; o1[r] = bh1; }
#pragma unroll 8
    for (int k = 0; k < 32; k++) {
        float w = Ws[k * 64 + lane], w2 = Ws[k * 64 + 32 + lane];
#pragma unroll
        for (int r = 0; r < 4; r++) { float v = __shfl_sync(FULL, xl0[r], k); o0[r] += v * w; o1[r] += v * w2; }
    }
#pragma unroll 8
    for (int k = 0; k < 32; k++) {
        int kk = 32 + k;
        float w = Ws[kk * 64 + lane], w2 = Ws[kk * 64 + 32 + lane];
#pragma unroll
        for (int r = 0; r < 4; r++) { float v = __shfl_sync(FULL, xl1[r], k); o0[r] += v * w; o1[r] += v * w2; }
    }
#pragma unroll 8
    for (int k = 0; k < 32; k++) {
        int kk = 64 + k;
        float w = Ws[kk * 64 + lane], w2 = Ws[kk * 64 + 32 + lane];
#pragma unroll
        for (int r = 0; r < 4; r++) { float v = __shfl_sync(FULL, sv0[r], k); o0[r] += v * w; o1[r] += v * w2; }
    }
#pragma unroll 8
    for (int k = 0; k < 32; k++) {
        int kk = 96 + k;
        float w = Ws[kk * 64 + lane], w2 = Ws[kk * 64 + 32 + lane];
#pragma unroll
        for (int r = 0; r < 4; r++) { float v = __shfl_sync(FULL, sv1[r], k); o0[r] += v * w; o1[r] += v * w2; }
    }
    if (xl_out) {
#pragma unroll
        for (int r = 0; r < 4; r++) {
            int row = r0 + r;
            if (row >= n) break;
            xl_out[row * 64 + lane] = xl0[r];
            xl_out[row * 64 + 32 + lane] = xl1[r];
        }
    }
    int nvalid = min(n - r0, 4);
    if (nvalid == 4 && bidx[0] == bidx[1] && bidx[1] == bidx[2] && bidx[2] == bidx[3]) {
        float p0 = o0[0] + o0[1] + o0[2] + o0[3];
        float p1 = o1[0] + o1[1] + o1[2] + o1[3];
        atomicAdd(&pooled[bidx[0] * 64 + lane], p0);
        atomicAdd(&pooled[bidx[0] * 64 + 32 + lane], p1);
    } else {
        for (int r = 0; r < nvalid; r++) {
            atomicAdd(&pooled[bidx[r] * 64 + lane], o0[r]);
            atomicAdd(&pooled[bidx[r] * 64 + 32 + lane], o1[r]);
        }
    }
}

// ---------------------------------------------------------------
extern "C" void kernel_launch(void* const* d_in, const int* in_sizes, int n_in,
                              void* d_out, int out_size) {
    int ix, is_, iW1, iW2, iGa, iBe, iWg, iBg, iWh, iBh, iEi, iBa;
    if (n_in >= 2 && in_sizes[0] == in_sizes[1]) {
        ix = 0; is_ = 1; iW1 = 2; iW2 = 3; iGa = 4; iBe = 5;
        iWg = 6; iBg = 7; iWh = 8; iBh = 9; iEi = 10; iBa = 11;
    } else {
        iW1 = 0; iW2 = 1; iWg = 2; iWh = 3; iBa = 4; iBe = 5;
        iBg = 6; iBh = 7; iEi = 8; iGa = 9; is_ = 10; ix = 11;
    }

    const float* x     = (const float*)d_in[ix];
    const float* s     = (const float*)d_in[is_];
    const float* W1    = (const float*)d_in[iW1];
    const float* W2    = (const float*)d_in[iW2];
    const float* gamma = (const float*)d_in[iGa];
    const float* beta  = (const float*)d_in[iBe];
    const float* Wg    = (const float*)d_in[iWg];
    const float* bg    = (const float*)d_in[iBg];
    const float* Wh    = (const float*)d_in[iWh];
    const float* bh    = (const float*)d_in[iBh];
    const int* eraw    = (const int*)d_in[iEi];
    const int* braw    = (const int*)d_in[iBa];
    float* out = (float*)d_out;

    int n = in_sizes[ix] / 64;
    int E = in_sizes[iEi] / 2;
    if (n > MAXN) n = MAXN;
    if (E > MAXE) E = MAXE;

    // ---- output layout resolution ----
    float* pooledPtr;
    float* xlocalPtr;
    int G;
    float* gpool;
    cudaGetSymbolAddress((void**)&gpool, g_pooled);
    if (out_size > n * 64) {
        G = out_size / 64 - n;
        pooledPtr = out;
        xlocalPtr = out + (long)G * 64;
    } else if (out_size == n * 64) {
        G = 64;
        pooledPtr = gpool;
        xlocalPtr = out;
    } else {
        G = out_size / 64;
        pooledPtr = out;
        xlocalPtr = nullptr;
    }
    if (G > 128) G = 128;
    if (G < 1) G = 1;

    int gemmBlocks = (((n + 3) / 4) + 7) / 8;
    int nodeBlocks = (n + 7) / 8;
    int cvtBlocks = ((E > n ? E : n) + 255) / 256;
    float* d_M;
    cudaGetSymbolAddress((void**)&d_M, g_M);

    // setup
    k_detect<<<1, 256>>>(eraw, 2 * E);
    k_convert<<<cvtBlocks, 256>>>(eraw, braw, E, n);
    k_zero<<<(n + 255) / 256, 256>>>(pooledPtr, n, G);
    k_deg<<<(E + 255) / 256, 256>>>(E);
    k_scan<<<1, 1024>>>(n);
    k_fill<<<(E + 255) / 256, 256>>>(E);
    k_precompute<<<128, 64>>>(W1, W2);

    // layer 0
    k1_gemm<<<gemmBlocks, 256>>>(x, s, W1, Wg, n);
    k_gather<<<nodeBlocks, 256>>>(n);
    // layer 1 (fused with layer-0 MLP second linear)
    k1_fused<<<gemmBlocks, 256>>>(d_M, W1 + 1 * 128 * 64 + 64 * 64, Wg + 1 * 64 * 64, bg, n);
    k_gather<<<nodeBlocks, 256>>>(n);
    // layer 2
    k1_fused<<<gemmBlocks, 256>>>(d_M + 4096, W1 + 2 * 128 * 64 + 64 * 64, Wg + 2 * 64 * 64, bg + 64, n);
    k_gather<<<nodeBlocks, 256>>>(n);
    // tail
    k3_mlp<<<gemmBlocks, 256>>>(W2 + 2 * 64 * 64, bg + 2 * 64, n);
    k_bn<<<1, 64>>>(n);
    k_final<<<gemmBlocks, 256>>>(gamma + 2 * 64, beta + 2 * 64, Wh, bh,
                                 pooledPtr, xlocalPtr, n, G);
}

// round 10
// speedup vs baseline: 1.2088x; 1.0204x over previous
#include <cuda_runtime.h>
#include <math.h>

#define FULL 0xffffffffu
constexpr int D = 64;
constexpr int MAXN = 50048;
constexpr int MAXE = 800000;
constexpr int MAXG = 128;

// ---- scratch (no allocations allowed) ----
__device__ float g_x[MAXN * D];
__device__ float g_s[MAXN * D];
__device__ float g_hs[MAXN * 2 * D];   // interleaved [hw(64) | dinv*sw(64)] per node
__device__ float g_aggx[MAXN * D];
__device__ float g_aggs[MAXN * D];
__device__ float g_dinv[MAXN];
__device__ float g_stats[2 * D];
__device__ float g_pooled[MAXG * D];
__device__ float g_M[2 * D * D];       // W2_l @ W1_{l+1}[0:64,:]
__device__ float g_Sla[MAXG * D];
__device__ float g_St[MAXG * D];
__device__ float g_C[D * D];
__device__ float g_cntf[MAXG];
__device__ int g_src[MAXE];
__device__ int g_dst[MAXE];
__device__ int g_csr[MAXE];
__device__ int g_batch[MAXN];
__device__ int g_degi[MAXN];
__device__ int g_rowstart[MAXN + 1];
__device__ int g_cursor[MAXN];
__device__ int g_is64;

// ---------------------------------------------------------------
__global__ void k_detect(const int* __restrict__ eraw, int totalInts) {
    __shared__ int anyNZ;
    if (threadIdx.x == 0) anyNZ = 0;
    __syncthreads();
    int limit = min(totalInts, 4096);
    for (int i = threadIdx.x * 2 + 1; i < limit; i += 512)
        if (eraw[i] != 0) anyNZ = 1;
    __syncthreads();
    if (threadIdx.x == 0) g_is64 = anyNZ ? 0 : 1;
}

__global__ void k_zero(float* pooled, int n, int G) {
    int i = blockIdx.x * blockDim.x + threadIdx.x;
    if (i < n) g_degi[i] = 0;
    if (i < 2 * D) g_stats[i] = 0.f;
    if (i < G * D) pooled[i] = 0.f;
    if (i < MAXG * D) { g_Sla[i] = 0.f; g_St[i] = 0.f; }
    if (i < D * D) g_C[i] = 0.f;
    if (i < MAXG) g_cntf[i] = 0.f;
}

// convert indices (+ degree histogram fused in)
__global__ void k_convert(const int* __restrict__ eraw, const int* __restrict__ braw,
                          int E, int n) {
    int i = blockIdx.x * blockDim.x + threadIdx.x;
    bool is64 = (g_is64 != 0);
    if (i < E) {
        int sv = is64 ? eraw[2 * i] : eraw[i];
        int dv = is64 ? eraw[2 * (E + i)] : eraw[E + i];
        if ((unsigned)sv >= (unsigned)n) sv = 0;
        if ((unsigned)dv >= (unsigned)n) dv = 0;
        g_src[i] = sv;
        g_dst[i] = dv;
        atomicAdd(&g_degi[dv], 1);
    }
    if (i < n) g_batch[i] = is64 ? braw[2 * i] : braw[i];
}

// one-block scan: rowstart (exclusive), cursor copy, dinv
__global__ void k_scan(int n) {
    __shared__ int ssum[1024];
    int t = threadIdx.x;
    int chunk = (n + 1023) / 1024;
    int b0 = t * chunk;
    int hi = min(b0 + chunk, n);
    int local = 0;
    for (int i = b0; i < hi; i++) local += g_degi[i];
    ssum[t] = local;
    __syncthreads();
    for (int off = 1; off < 1024; off <<= 1) {
        int v = (t >= off) ? ssum[t - off] : 0;
        __syncthreads();
        ssum[t] += v;
        __syncthreads();
    }
    int run = (t == 0) ? 0 : ssum[t - 1];
    for (int i = b0; i < hi; i++) {
        g_rowstart[i] = run;
        g_cursor[i] = run;
        g_dinv[i] = rsqrtf((float)g_degi[i] + 1.0f);
        run += g_degi[i];
    }
    if (t == 0) g_rowstart[n] = ssum[1023];
}

__global__ void k_fill(int E) {
    int e = blockIdx.x * blockDim.x + threadIdx.x;
    if (e < E) {
        int pos = atomicAdd(&g_cursor[g_dst[e]], 1);
        g_csr[pos] = g_src[e];
    }
}

// ---------------------------------------------------------------
// M[l] = W2_l @ W1_{l+1}[0:64,:]
__global__ void k_precompute(const float* __restrict__ W1, const float* __restrict__ W2) {
    int b = blockIdx.x;
    int l = b >> 6, k = b & 63;
    int c = threadIdx.x;
    const float* W2l = W2 + l * 4096;
    const float* W1a = W1 + (l + 1) * 8192;
    float acc = 0.f;
#pragma unroll 16
    for (int j = 0; j < 64; j++) acc = fmaf(W2l[k * 64 + j], W1a[j * 64 + c], acc);
    g_M[l * 4096 + k * 64 + c] = acc;
}

// ---------------------------------------------------------------
// Layer-0 GEMM: hw = x@W1a + s@W1b ; sws = dinv*(s@Wg). Interleaved store.
__global__ void k1_gemm(const float* __restrict__ xin, const float* __restrict__ sin,
                        const float* __restrict__ W1, const float* __restrict__ Wg, int n) {
    __shared__ float W1s[128 * 64];
    __shared__ float Wgs[64 * 64];
    int tid = threadIdx.x;
    for (int i = tid; i < 128 * 64; i += 256) W1s[i] = W1[i];
    for (int i = tid; i < 64 * 64; i += 256) Wgs[i] = Wg[i];
    __syncthreads();
    int lane = tid & 31;
    int warp = blockIdx.x * 8 + (tid >> 5);
    int r0 = warp * 4;
    if (r0 >= n) return;

    float xa[4], xb[4], sa[4], sb[4];
#pragma unroll
    for (int r = 0; r < 4; r++) {
        int row = min(r0 + r, n - 1);
        xa[r] = xin[row * 64 + lane];  xb[r] = xin[row * 64 + 32 + lane];
        sa[r] = sin[row * 64 + lane];  sb[r] = sin[row * 64 + 32 + lane];
    }
    float h0[4] = {0,0,0,0}, h1[4] = {0,0,0,0}, w0[4] = {0,0,0,0}, w1[4] = {0,0,0,0};
#pragma unroll 8
    for (int k = 0; k < 32; k++) {
        float wa = W1s[k * 64 + lane],          wa2 = W1s[k * 64 + 32 + lane];
        float wb = W1s[(64 + k) * 64 + lane],   wb2 = W1s[(64 + k) * 64 + 32 + lane];
        float wg = Wgs[k * 64 + lane],          wg2 = Wgs[k * 64 + 32 + lane];
#pragma unroll
        for (int r = 0; r < 4; r++) {
            float xv = __shfl_sync(FULL, xa[r], k);
            float sv = __shfl_sync(FULL, sa[r], k);
            h0[r] += xv * wa;  h0[r] += sv * wb;
            h1[r] += xv * wa2; h1[r] += sv * wb2;
            w0[r] += sv * wg;  w1[r] += sv * wg2;
        }
    }
#pragma unroll 8
    for (int k = 0; k < 32; k++) {
        int kk = k + 32;
        float wa = W1s[kk * 64 + lane],          wa2 = W1s[kk * 64 + 32 + lane];
        float wb = W1s[(64 + kk) * 64 + lane],   wb2 = W1s[(64 + kk) * 64 + 32 + lane];
        float wg = Wgs[kk * 64 + lane],          wg2 = Wgs[kk * 64 + 32 + lane];
#pragma unroll
        for (int r = 0; r < 4; r++) {
            float xv = __shfl_sync(FULL, xb[r], k);
            float sv = __shfl_sync(FULL, sb[r], k);
            h0[r] += xv * wa;  h0[r] += sv * wb;
            h1[r] += xv * wa2; h1[r] += sv * wb2;
            w0[r] += sv * wg;  w1[r] += sv * wg2;
        }
    }
#pragma unroll
    for (int r = 0; r < 4; r++) {
        int row = r0 + r;
        if (row >= n) break;
        float dvr = g_dinv[row];
        int base = row * 128;
        g_hs[base + lane] = h0[r];        g_hs[base + 32 + lane] = h1[r];
        g_hs[base + 64 + lane] = dvr * w0[r]; g_hs[base + 96 + lane] = dvr * w1[r];
    }
}

// ---------------------------------------------------------------
// Fused layer GEMM (layers 1,2): a = leaky(aggx), t = tanh(aggs + bg_prev)
// hw = a@M + t@W1b ; sws = dinv*(t@Wg). Interleaved store.
__global__ void k1_fused(const float* __restrict__ M, const float* __restrict__ W1b,
                         const float* __restrict__ Wg, const float* __restrict__ bgp, int n) {
    __shared__ float Ms[64 * 64];
    __shared__ float Bs[64 * 64];
    __shared__ float Gs[64 * 64];
    int tid = threadIdx.x;
    for (int i = tid; i < 64 * 64; i += 256) { Ms[i] = M[i]; Bs[i] = W1b[i]; Gs[i] = Wg[i]; }
    __syncthreads();
    int lane = tid & 31;
    int warp = blockIdx.x * 8 + (tid >> 5);
    int r0 = warp * 4;
    if (r0 >= n) return;

    float b0v = bgp[lane], b1v = bgp[32 + lane];
    float aa[4], ab[4], ta[4], tb[4];
#pragma unroll
    for (int r = 0; r < 4; r++) {
        int row = min(r0 + r, n - 1);
        float v0 = g_aggx[row * 64 + lane], v1 = g_aggx[row * 64 + 32 + lane];
        aa[r] = v0 > 0.f ? v0 : 0.01f * v0;
        ab[r] = v1 > 0.f ? v1 : 0.01f * v1;
        ta[r] = tanhf(g_aggs[row * 64 + lane] + b0v);
        tb[r] = tanhf(g_aggs[row * 64 + 32 + lane] + b1v);
    }
    float h0[4] = {0,0,0,0}, h1[4] = {0,0,0,0}, w0[4] = {0,0,0,0}, w1[4] = {0,0,0,0};
#pragma unroll 8
    for (int k = 0; k < 32; k++) {
        float wa = Ms[k * 64 + lane], wa2 = Ms[k * 64 + 32 + lane];
        float wb = Bs[k * 64 + lane], wb2 = Bs[k * 64 + 32 + lane];
        float wg = Gs[k * 64 + lane], wg2 = Gs[k * 64 + 32 + lane];
#pragma unroll
        for (int r = 0; r < 4; r++) {
            float av = __shfl_sync(FULL, aa[r], k);
            float tv = __shfl_sync(FULL, ta[r], k);
            h0[r] += av * wa;  h0[r] += tv * wb;
            h1[r] += av * wa2; h1[r] += tv * wb2;
            w0[r] += tv * wg;  w1[r] += tv * wg2;
        }
    }
#pragma unroll 8
    for (int k = 0; k < 32; k++) {
        int kk = k + 32;
        float wa = Ms[kk * 64 + lane], wa2 = Ms[kk * 64 + 32 + lane];
        float wb = Bs[kk * 64 + lane], wb2 = Bs[kk * 64 + 32 + lane];
        float wg = Gs[kk * 64 + lane], wg2 = Gs[kk * 64 + 32 + lane];
#pragma unroll
        for (int r = 0; r < 4; r++) {
            float av = __shfl_sync(FULL, ab[r], k);
            float tv = __shfl_sync(FULL, tb[r], k);
            h0[r] += av * wa;  h0[r] += tv * wb;
            h1[r] += av * wa2; h1[r] += tv * wb2;
            w0[r] += tv * wg;  w1[r] += tv * wg2;
        }
    }
#pragma unroll
    for (int r = 0; r < 4; r++) {
        int row = r0 + r;
        if (row >= n) break;
        float dvr = g_dinv[row];
        int base = row * 128;
        g_hs[base + lane] = h0[r];        g_hs[base + 32 + lane] = h1[r];
        g_hs[base + 64 + lane] = dvr * w0[r]; g_hs[base + 96 + lane] = dvr * w1[r];
    }
}

// ---------------------------------------------------------------
// CSR gather: warp per dst node; each lane one float4 of the 512B node row.
// lanes 0-15 accumulate hw -> aggx; lanes 16-31 accumulate dinv-scaled sw,
// multiplied by dinv[d] at the end -> aggs.
__global__ void k_gather(int n) {
    int di = blockIdx.x * 8 + (threadIdx.x >> 5);
    if (di >= n) return;
    int lane = threadIdx.x & 31;
    const float4* hs = (const float4*)g_hs;
    float4 acc = hs[di * 32 + lane];            // self term
    int beg = g_rowstart[di], end = g_rowstart[di + 1];
    int j = beg;
    for (; j + 4 <= end; j += 4) {
        int s0 = g_csr[j], s1 = g_csr[j + 1], s2 = g_csr[j + 2], s3 = g_csr[j + 3];
        float4 v0 = hs[s0 * 32 + lane];
        float4 v1 = hs[s1 * 32 + lane];
        float4 v2 = hs[s2 * 32 + lane];
        float4 v3 = hs[s3 * 32 + lane];
        acc.x += v0.x + v1.x + v2.x + v3.x;
        acc.y += v0.y + v1.y + v2.y + v3.y;
        acc.z += v0.z + v1.z + v2.z + v3.z;
        acc.w += v0.w + v1.w + v2.w + v3.w;
    }
    for (; j < end; j++) {
        float4 v = hs[g_csr[j] * 32 + lane];
        acc.x += v.x; acc.y += v.y; acc.z += v.z; acc.w += v.w;
    }
    if (lane < 16) {
        ((float4*)g_aggx)[di * 16 + lane] = acc;
    } else {
        float dv = g_dinv[di];
        acc.x *= dv; acc.y *= dv; acc.z *= dv; acc.w *= dv;
        ((float4*)g_aggs)[di * 16 + lane - 16] = acc;
    }
}

// ---------------------------------------------------------------
// FAST TAIL (pooled-only): one pass over aggx/aggs.
// Accumulates: per-graph sums of la=leaky(aggx) and t=tanh(aggs+bg),
// graph counts, and covariance C = sum la la^T (for BN variance).
__global__ void k_tail(const float* __restrict__ bg, int n, int G) {
    __shared__ float la_s[128 * 64];   // 32KB
    int tid = threadIdx.x;
    int c = tid & 63, q = tid >> 6;
    int r0 = blockIdx.x * 128;
    float bgc = bg[c];
    float accL = 0.f, accT = 0.f, cntRun = 0.f;
    int curg = -1;
    for (int rr = q; rr < 128; rr += 4) {
        int r = r0 + rr;
        if (r < n) {
            float v = g_aggx[r * 64 + c];
            float la = v > 0.f ? v : 0.01f * v;
            la_s[rr * 64 + c] = la;
            float tv = tanhf(g_aggs[r * 64 + c] + bgc);
            int g = g_batch[r];
            if ((unsigned)g >= (unsigned)G) g = 0;
            if (g != curg) {
                if (curg >= 0) {
                    atomicAdd(&g_Sla[curg * 64 + c], accL);
                    atomicAdd(&g_St[curg * 64 + c], accT);
                    if (c == 0) atomicAdd(&g_cntf[curg], cntRun);
                }
                curg = g; accL = 0.f; accT = 0.f; cntRun = 0.f;
            }
            accL += la; accT += tv; cntRun += 1.f;
        } else {
            la_s[rr * 64 + c] = 0.f;
        }
    }
    if (curg >= 0) {
        atomicAdd(&g_Sla[curg * 64 + c], accL);
        atomicAdd(&g_St[curg * 64 + c], accT);
        if (c == 0) atomicAdd(&g_cntf[curg], cntRun);
    }
    __syncthreads();
    // covariance: thread computes a 4x4 tile of C
    int a0 = (tid >> 4) * 4, b0 = (tid & 15) * 4;
    float C00=0,C01=0,C02=0,C03=0, C10=0,C11=0,C12=0,C13=0;
    float C20=0,C21=0,C22=0,C23=0, C30=0,C31=0,C32=0,C33=0;
    for (int r = 0; r < 128; r++) {
        float4 va = *(const float4*)&la_s[r * 64 + a0];
        float4 vb = *(const float4*)&la_s[r * 64 + b0];
        C00 += va.x*vb.x; C01 += va.x*vb.y; C02 += va.x*vb.z; C03 += va.x*vb.w;
        C10 += va.y*vb.x; C11 += va.y*vb.y; C12 += va.y*vb.z; C13 += va.y*vb.w;
        C20 += va.z*vb.x; C21 += va.z*vb.y; C22 += va.z*vb.z; C23 += va.z*vb.w;
        C30 += va.w*vb.x; C31 += va.w*vb.y; C32 += va.w*vb.z; C33 += va.w*vb.w;
    }
    atomicAdd(&g_C[(a0+0)*64+b0+0], C00); atomicAdd(&g_C[(a0+0)*64+b0+1], C01);
    atomicAdd(&g_C[(a0+0)*64+b0+2], C02); atomicAdd(&g_C[(a0+0)*64+b0+3], C03);
    atomicAdd(&g_C[(a0+1)*64+b0+0], C10); atomicAdd(&g_C[(a0+1)*64+b0+1], C11);
    atomicAdd(&g_C[(a0+1)*64+b0+2], C12); atomicAdd(&g_C[(a0+1)*64+b0+3], C13);
    atomicAdd(&g_C[(a0+2)*64+b0+0], C20); atomicAdd(&g_C[(a0+2)*64+b0+1], C21);
    atomicAdd(&g_C[(a0+2)*64+b0+2], C22); atomicAdd(&g_C[(a0+2)*64+b0+3], C23);
    atomicAdd(&g_C[(a0+3)*64+b0+0], C30); atomicAdd(&g_C[(a0+3)*64+b0+1], C31);
    atomicAdd(&g_C[(a0+3)*64+b0+2], C32); atomicAdd(&g_C[(a0+3)*64+b0+3], C33);
}

// BN stats from covariance: mean_c = (sum_la @ W2)_c / n;
// var_c = (W2^T C W2)_cc / n - mean_c^2
__global__ void k_bn2(const float* __restrict__ W2, int n, int G) {
    __shared__ float Cs[4096];
    __shared__ float W2s[4096];
    __shared__ float qpart[256];
    __shared__ float Tla[64];
    int tid = threadIdx.x;
    for (int i = tid; i < 4096; i += 256) { Cs[i] = g_C[i]; W2s[i] = W2[i]; }
    __syncthreads();
    int c = tid & 63, p = tid >> 6;
    float part = 0.f;
    for (int r = p; r < 64; r += 4) {
        float inner = 0.f;
#pragma unroll 16
        for (int k = 0; k < 64; k++) inner = fmaf(Cs[r * 64 + k], W2s[k * 64 + c], inner);
        part = fmaf(W2s[r * 64 + c], inner, part);
    }
    qpart[tid] = part;
    if (tid < 64) {
        float t = 0.f;
        for (int g = 0; g < G; g++) t += g_Sla[g * 64 + tid];
        Tla[tid] = t;
    }
    __syncthreads();
    if (tid < 64) {
        float quad = qpart[tid] + qpart[64 + tid] + qpart[128 + tid] + qpart[192 + tid];
        float mean = 0.f;
#pragma unroll 16
        for (int k = 0; k < 64; k++) mean = fmaf(Tla[k], W2s[k * 64 + tid], mean);
        mean /= (float)n;
        float var = quad / (float)n - mean * mean;
        g_stats[tid] = mean;
        g_stats[64 + tid] = rsqrtf(var + 1e-4f);
    }
}

// pooled[g] = (gamma*iv*(Sla[g]@W2 - cnt*m) + cnt*beta) @ Wh_top
//            + St[g] @ Wh_bot + cnt*bh
__global__ void k_pool(const float* __restrict__ W2, const float* __restrict__ gamma,
                       const float* __restrict__ beta, const float* __restrict__ Wh,
                       const float* __restrict__ bh, float* __restrict__ pooled) {
    __shared__ float Sl[64], Stm[64], xls[64];
    int g = blockIdx.x;
    int c = threadIdx.x;
    Sl[c] = g_Sla[g * 64 + c];
    Stm[c] = g_St[g * 64 + c];
    float cnt = g_cntf[g];
    __syncthreads();
    float sx3 = 0.f;
#pragma unroll 16
    for (int k = 0; k < 64; k++) sx3 = fmaf(Sl[k], W2[k * 64 + c], sx3);
    float m = g_stats[c], iv = g_stats[64 + c];
    xls[c] = gamma[c] * iv * (sx3 - cnt * m) + cnt * beta[c];
    __syncthreads();
    float o = cnt * bh[c];
#pragma unroll 16
    for (int k = 0; k < 64; k++) o = fmaf(xls[k], Wh[k * 64 + c], o);
#pragma unroll 16
    for (int k = 0; k < 64; k++) o = fmaf(Stm[k], Wh[(64 + k) * 64 + c], o);
    pooled[g * 64 + c] = o;
}

// ---------------------------------------------------------------
// FALLBACK PATH (x_local output required): per-node x3/s + BN + final
__global__ void k3_mlp(const float* __restrict__ W2, const float* __restrict__ bg, int n) {
    __shared__ float Ws[64 * 64];
    __shared__ float shst[128];
    int tid = threadIdx.x;
    for (int i = tid; i < 64 * 64; i += 256) Ws[i] = W2[i];
    if (tid < 128) shst[tid] = 0.f;
    __syncthreads();
    int lane = tid & 31;
    int warp = blockIdx.x * 8 + (tid >> 5);
    int r0 = warp * 4;
    bool active = (r0 < n);
    float sum0 = 0.f, sum1 = 0.f, sq0 = 0.f, sq1 = 0.f;
    if (active) {
        float a0[4], a1[4];
#pragma unroll
        for (int r = 0; r < 4; r++) {
            int row = min(r0 + r, n - 1);
            float v0 = g_aggx[row * 64 + lane], v1 = g_aggx[row * 64 + 32 + lane];
            a0[r] = v0 > 0.f ? v0 : 0.01f * v0;
            a1[r] = v1 > 0.f ? v1 : 0.01f * v1;
        }
        float o0[4] = {0,0,0,0}, o1[4] = {0,0,0,0};
#pragma unroll 8
        for (int k = 0; k < 32; k++) {
            float w = Ws[k * 64 + lane], w2 = Ws[k * 64 + 32 + lane];
#pragma unroll
            for (int r = 0; r < 4; r++) {
                float xv = __shfl_sync(FULL, a0[r], k);
                o0[r] += xv * w; o1[r] += xv * w2;
            }
        }
#pragma unroll 8
        for (int k = 0; k < 32; k++) {
            int kk = k + 32;
            float w = Ws[kk * 64 + lane], w2 = Ws[kk * 64 + 32 + lane];
#pragma unroll
            for (int r = 0; r < 4; r++) {
                float xv = __shfl_sync(FULL, a1[r], k);
                o0[r] += xv * w; o1[r] += xv * w2;
            }
        }
        float b0 = bg[lane], b1 = bg[32 + lane];
#pragma unroll
        for (int r = 0; r < 4; r++) {
            int row = r0 + r;
            if (row >= n) break;
            g_x[row * 64 + lane] = o0[r]; g_x[row * 64 + 32 + lane] = o1[r];
            g_s[row * 64 + lane]      = tanhf(g_aggs[row * 64 + lane] + b0);
            g_s[row * 64 + 32 + lane] = tanhf(g_aggs[row * 64 + 32 + lane] + b1);
            sum0 += o0[r]; sq0 += o0[r] * o0[r];
            sum1 += o1[r]; sq1 += o1[r] * o1[r];
        }
    }
    atomicAdd(&shst[lane], sum0);
    atomicAdd(&shst[32 + lane], sum1);
    atomicAdd(&shst[64 + lane], sq0);
    atomicAdd(&shst[96 + lane], sq1);
    __syncthreads();
    if (tid < 128) atomicAdd(&g_stats[tid], shst[tid]);
}

__global__ void k_bn(int n) {
    int c = threadIdx.x;
    float mean = g_stats[c] / (float)n;
    float var = g_stats[64 + c] / (float)n - mean * mean;
    g_stats[c] = mean;
    g_stats[64 + c] = rsqrtf(var + 1e-4f);
}

__global__ void k_final(const float* __restrict__ gamma, const float* __restrict__ beta,
                        const float* __restrict__ Wh, const float* __restrict__ bh,
                        float* __restrict__ pooled, float* __restrict__ xl_out,
                        int n, int G) {
    __shared__ float Ws[128 * 64];
    int tid = threadIdx.x;
    for (int i = tid; i < 128 * 64; i += 256) Ws[i] = Wh[i];
    __syncthreads();
    int lane = tid & 31;
    int warp = blockIdx.x * 8 + (tid >> 5);
    int r0 = warp * 4;
    if (r0 >= n) return;
    float m0 = g_stats[lane],      m1 = g_stats[32 + lane];
    float i0 = g_stats[64 + lane], i1 = g_stats[96 + lane];
    float ga0 = gamma[lane], ga1 = gamma[32 + lane];
    float be0 = beta[lane],  be1 = beta[32 + lane];
    float xl0[4], xl1[4], sv0[4], sv1[4];
    int bidx[4];
#pragma unroll
    for (int r = 0; r < 4; r++) {
        int row = min(r0 + r, n - 1);
        xl0[r] = ga0 * (g_x[row * 64 + lane] - m0) * i0 + be0;
        xl1[r] = ga1 * (g_x[row * 64 + 32 + lane] - m1) * i1 + be1;
        sv0[r] = g_s[row * 64 + lane];
        sv1[r] = g_s[row * 64 + 32 + lane];
        int b = g_batch[row];
        bidx[r] = ((unsigned)b < (unsigned)G) ? b : 0;
    }
    float bh0 = bh[lane], bh1 = bh[32 + lane];
    float o0[4], o1[4];
#pragma unroll
    for (int r = 0; r < 4; r++) { o0[r] = bh0; o1[r] = bh1; }
#pragma unroll 8
    for (int k = 0; k < 32; k++) {
        float w = Ws[k * 64 + lane], w2 = Ws[k * 64 + 32 + lane];
#pragma unroll
        for (int r = 0; r < 4; r++) { float v = __shfl_sync(FULL, xl0[r], k); o0[r] += v * w; o1[r] += v * w2; }
    }
#pragma unroll 8
    for (int k = 0; k < 32; k++) {
        int kk = 32 + k;
        float w = Ws[kk * 64 + lane], w2 = Ws[kk * 64 + 32 + lane];
#pragma unroll
        for (int r = 0; r < 4; r++) { float v = __shfl_sync(FULL, xl1[r], k); o0[r] += v * w; o1[r] += v * w2; }
    }
#pragma unroll 8
    for (int k = 0; k < 32; k++) {
        int kk = 64 + k;
        float w = Ws[kk * 64 + lane], w2 = Ws[kk * 64 + 32 + lane];
#pragma unroll
        for (int r = 0; r < 4; r++) { float v = __shfl_sync(FULL, sv0[r], k); o0[r] += v * w; o1[r] += v * w2; }
    }
#pragma unroll 8
    for (int k = 0; k < 32; k++) {
        int kk = 96 + k;
        float w = Ws[kk * 64 + lane], w2 = Ws[kk * 64 + 32 + lane];
#pragma unroll
        for (int r = 0; r < 4; r++) { float v = __shfl_sync(FULL, sv1[r], k); o0[r] += v * w; o1[r] += v * w2; }
    }
    if (xl_out) {
#pragma unroll
        for (int r = 0; r < 4; r++) {
            int row = r0 + r;
            if (row >= n) break;
            xl_out[row * 64 + lane] = xl0[r];
            xl_out[row * 64 + 32 + lane] = xl1[r];
        }
    }
    int nvalid = min(n - r0, 4);
    for (int r = 0; r < nvalid; r++) {
        atomicAdd(&pooled[bidx[r] * 64 + lane], o0[r]);
        atomicAdd(&pooled[bidx[r] * 64 + 32 + lane], o1[r]);
    }
}

// ---------------------------------------------------------------
extern "C" void kernel_launch(void* const* d_in, const int* in_sizes, int n_in,
                              void* d_out, int out_size) {
    int ix, is_, iW1, iW2, iGa, iBe, iWg, iBg, iWh, iBh, iEi, iBa;
    if (n_in >= 2 && in_sizes[0] == in_sizes[1]) {
        ix = 0; is_ = 1; iW1 = 2; iW2 = 3; iGa = 4; iBe = 5;
        iWg = 6; iBg = 7; iWh = 8; iBh = 9; iEi = 10; iBa = 11;
    } else {
        iW1 = 0; iW2 = 1; iWg = 2; iWh = 3; iBa = 4; iBe = 5;
        iBg = 6; iBh = 7; iEi = 8; iGa = 9; is_ = 10; ix = 11;
    }

    const float* x     = (const float*)d_in[ix];
    const float* s     = (const float*)d_in[is_];
    const float* W1    = (const float*)d_in[iW1];
    const float* W2    = (const float*)d_in[iW2];
    const float* gamma = (const float*)d_in[iGa];
    const float* beta  = (const float*)d_in[iBe];
    const float* Wg    = (const float*)d_in[iWg];
    const float* bg    = (const float*)d_in[iBg];
    const float* Wh    = (const float*)d_in[iWh];
    const float* bh    = (const float*)d_in[iBh];
    const int* eraw    = (const int*)d_in[iEi];
    const int* braw    = (const int*)d_in[iBa];
    float* out = (float*)d_out;

    int n = in_sizes[ix] / 64;
    int E = in_sizes[iEi] / 2;
    if (n > MAXN) n = MAXN;
    if (E > MAXE) E = MAXE;

    // ---- output layout resolution ----
    float* pooledPtr;
    float* xlocalPtr;
    int G;
    float* gpool;
    cudaGetSymbolAddress((void**)&gpool, g_pooled);
    if (out_size > n * 64) {
        G = out_size / 64 - n;
        pooledPtr = out;
        xlocalPtr = out + (long)G * 64;
    } else if (out_size == n * 64) {
        G = 64;
        pooledPtr = gpool;
        xlocalPtr = out;
    } else {
        G = out_size / 64;
        pooledPtr = out;
        xlocalPtr = nullptr;
    }
    if (G > MAXG) G = MAXG;
    if (G < 1) G = 1;

    int gemmBlocks = (((n + 3) / 4) + 7) / 8;
    int nodeBlocks = (n + 7) / 8;
    int cvtBlocks = ((E > n ? E : n) + 255) / 256;
    float* d_M;
    cudaGetSymbolAddress((void**)&d_M, g_M);

    // setup
    k_detect<<<1, 256>>>(eraw, 2 * E);
    k_zero<<<(n + 255) / 256, 256>>>(pooledPtr, n, G);
    k_convert<<<cvtBlocks, 256>>>(eraw, braw, E, n);
    k_scan<<<1, 1024>>>(n);
    k_fill<<<(E + 255) / 256, 256>>>(E);
    k_precompute<<<128, 64>>>(W1, W2);

    // layer 0
    k1_gemm<<<gemmBlocks, 256>>>(x, s, W1, Wg, n);
    k_gather<<<nodeBlocks, 256>>>(n);
    // layer 1 (fused with layer-0 MLP second linear)
    k1_fused<<<gemmBlocks, 256>>>(d_M, W1 + 1 * 128 * 64 + 64 * 64, Wg + 1 * 64 * 64, bg, n);
    k_gather<<<nodeBlocks, 256>>>(n);
    // layer 2
    k1_fused<<<gemmBlocks, 256>>>(d_M + 4096, W1 + 2 * 128 * 64 + 64 * 64, Wg + 2 * 64 * 64, bg + 64, n);
    k_gather<<<nodeBlocks, 256>>>(n);

    if (xlocalPtr == nullptr) {
        // FAST TAIL: pooled-only, x3/s never materialized
        k_tail<<<(n + 127) / 128, 256>>>(bg + 2 * 64, n, G);
        k_bn2<<<1, 256>>>(W2 + 2 * 64 * 64, n, G);
        k_pool<<<G, 64>>>(W2 + 2 * 64 * 64, gamma + 2 * 64, beta + 2 * 64, Wh, bh, pooledPtr);
    } else {
        // fallback: x_local required
        k3_mlp<<<gemmBlocks, 256>>>(W2 + 2 * 64 * 64, bg + 2 * 64, n);
        k_bn<<<1, 64>>>(n);
        k_final<<<gemmBlocks, 256>>>(gamma + 2 * 64, beta + 2 * 64, Wh, bh,
                                     pooledPtr, xlocalPtr, n, G);
    }
}

// round 11
// speedup vs baseline: 1.4834x; 1.2272x over previous
#include <cuda_runtime.h>
#include <math.h>

#define FULL 0xffffffffu
constexpr int D = 64;
constexpr int MAXN = 50048;
constexpr int MAXE = 800000;
constexpr int MAXG = 128;
constexpr int SCAN_CHUNK = 16;
constexpr int SCAN_BLOCK = 256;
constexpr int SCAN_ELEMS = SCAN_BLOCK * SCAN_CHUNK;   // 4096 per block

// ---- scratch (no allocations allowed) ----
__device__ float g_x[MAXN * D];
__device__ float g_s[MAXN * D];
__device__ float g_hs[MAXN * 2 * D];   // interleaved [hw(64) | dinv*sw(64)] per node
__device__ float g_aggx[MAXN * D];
__device__ float g_aggs[MAXN * D];
__device__ float g_dinv[MAXN];
__device__ float g_stats[2 * D];
__device__ float g_pooled[MAXG * D];
__device__ float g_M[2 * D * D];       // W2_l @ W1_{l+1}[0:64,:]
__device__ float g_Sla[MAXG * D];
__device__ float g_St[MAXG * D];
__device__ float g_C[D * D];
__device__ float g_cntf[MAXG];
__device__ int g_src[MAXE];
__device__ int g_dst[MAXE];
__device__ int g_csr[MAXE];
__device__ int g_batch[MAXN];
__device__ int g_degi[MAXN];
__device__ int g_rowstart[MAXN + 1];
__device__ int g_cursor[MAXN];
__device__ int g_blocksum[64];
__device__ int g_blockoff[64];
__device__ int g_is64;

// ---------------------------------------------------------------
__global__ void k_detect(const int* __restrict__ eraw, int totalInts) {
    __shared__ int anyNZ;
    if (threadIdx.x == 0) anyNZ = 0;
    __syncthreads();
    int limit = min(totalInts, 4096);
    for (int i = threadIdx.x * 2 + 1; i < limit; i += 512)
        if (eraw[i] != 0) anyNZ = 1;
    __syncthreads();
    if (threadIdx.x == 0) g_is64 = anyNZ ? 0 : 1;
}

__global__ void k_zero(float* pooled, int n, int G) {
    int i = blockIdx.x * blockDim.x + threadIdx.x;
    if (i < n) g_degi[i] = 0;
    if (i < 2 * D) g_stats[i] = 0.f;
    if (i < G * D) pooled[i] = 0.f;
    if (i < MAXG * D) { g_Sla[i] = 0.f; g_St[i] = 0.f; }
    if (i < D * D) g_C[i] = 0.f;
    if (i < MAXG) g_cntf[i] = 0.f;
}

// convert indices (+ degree histogram fused in)
__global__ void k_convert(const int* __restrict__ eraw, const int* __restrict__ braw,
                          int E, int n) {
    int i = blockIdx.x * blockDim.x + threadIdx.x;
    bool is64 = (g_is64 != 0);
    if (i < E) {
        int sv = is64 ? eraw[2 * i] : eraw[i];
        int dv = is64 ? eraw[2 * (E + i)] : eraw[E + i];
        if ((unsigned)sv >= (unsigned)n) sv = 0;
        if ((unsigned)dv >= (unsigned)n) dv = 0;
        g_src[i] = sv;
        g_dst[i] = dv;
        atomicAdd(&g_degi[dv], 1);
    }
    if (i < n) g_batch[i] = is64 ? braw[2 * i] : braw[i];
}

// ---------------------------------------------------------------
// 3-phase parallel exclusive scan over g_degi -> rowstart/cursor/dinv
__global__ void k_scan1(int n) {
    __shared__ int ts[SCAN_BLOCK];
    int t = threadIdx.x, b = blockIdx.x;
    int base = b * SCAN_ELEMS + t * SCAN_CHUNK;
    int sum = 0;
#pragma unroll
    for (int i = 0; i < SCAN_CHUNK; i++) {
        int idx = base + i;
        if (idx < n) sum += g_degi[idx];
    }
    ts[t] = sum;
    __syncthreads();
    for (int off = 128; off > 0; off >>= 1) {
        if (t < off) ts[t] += ts[t + off];
        __syncthreads();
    }
    if (t == 0) g_blocksum[b] = ts[0];
}

__global__ void k_scan2(int nb, int n) {
    __shared__ int sh[64];
    int t = threadIdx.x;   // 64 threads
    int v = (t < nb) ? g_blocksum[t] : 0;
    sh[t] = v;
    __syncthreads();
    for (int off = 1; off < 64; off <<= 1) {
        int vv = (t >= off) ? sh[t - off] : 0;
        __syncthreads();
        sh[t] += vv;
        __syncthreads();
    }
    if (t < nb) g_blockoff[t] = sh[t] - v;   // exclusive
    if (t == 63) g_rowstart[n] = sh[63];     // total
}

__global__ void k_scan3(int n) {
    __shared__ int ts[SCAN_BLOCK];
    int t = threadIdx.x, b = blockIdx.x;
    int base = b * SCAN_ELEMS + t * SCAN_CHUNK;
    int deg[SCAN_CHUNK];
    int sum = 0;
#pragma unroll
    for (int i = 0; i < SCAN_CHUNK; i++) {
        int idx = base + i;
        deg[i] = (idx < n) ? g_degi[idx] : 0;
        sum += deg[i];
    }
    ts[t] = sum;
    __syncthreads();
    for (int off = 1; off < SCAN_BLOCK; off <<= 1) {
        int v = (t >= off) ? ts[t - off] : 0;
        __syncthreads();
        ts[t] += v;
        __syncthreads();
    }
    int run = g_blockoff[b] + ts[t] - sum;   // exclusive start for this thread
#pragma unroll
    for (int i = 0; i < SCAN_CHUNK; i++) {
        int idx = base + i;
        if (idx < n) {
            g_rowstart[idx] = run;
            g_cursor[idx] = run;
            g_dinv[idx] = rsqrtf((float)deg[i] + 1.0f);
            run += deg[i];
        }
    }
}

__global__ void k_fill(int E) {
    int e = blockIdx.x * blockDim.x + threadIdx.x;
    if (e < E) {
        int pos = atomicAdd(&g_cursor[g_dst[e]], 1);
        g_csr[pos] = g_src[e];
    }
}

// ---------------------------------------------------------------
// M[l] = W2_l @ W1_{l+1}[0:64,:]
__global__ void k_precompute(const float* __restrict__ W1, const float* __restrict__ W2) {
    int b = blockIdx.x;
    int l = b >> 6, k = b & 63;
    int c = threadIdx.x;
    const float* W2l = W2 + l * 4096;
    const float* W1a = W1 + (l + 1) * 8192;
    float acc = 0.f;
#pragma unroll 16
    for (int j = 0; j < 64; j++) acc = fmaf(W2l[k * 64 + j], W1a[j * 64 + c], acc);
    g_M[l * 4096 + k * 64 + c] = acc;
}

// ---------------------------------------------------------------
// Layer-0 GEMM: hw = x@W1a + s@W1b ; sws = dinv*(s@Wg). Interleaved store.
__global__ void k1_gemm(const float* __restrict__ xin, const float* __restrict__ sin,
                        const float* __restrict__ W1, const float* __restrict__ Wg, int n) {
    __shared__ float W1s[128 * 64];
    __shared__ float Wgs[64 * 64];
    int tid = threadIdx.x;
    for (int i = tid; i < 128 * 64; i += 256) W1s[i] = W1[i];
    for (int i = tid; i < 64 * 64; i += 256) Wgs[i] = Wg[i];
    __syncthreads();
    int lane = tid & 31;
    int warp = blockIdx.x * 8 + (tid >> 5);
    int r0 = warp * 4;
    if (r0 >= n) return;

    float xa[4], xb[4], sa[4], sb[4];
#pragma unroll
    for (int r = 0; r < 4; r++) {
        int row = min(r0 + r, n - 1);
        xa[r] = xin[row * 64 + lane];  xb[r] = xin[row * 64 + 32 + lane];
        sa[r] = sin[row * 64 + lane];  sb[r] = sin[row * 64 + 32 + lane];
    }
    float h0[4] = {0,0,0,0}, h1[4] = {0,0,0,0}, w0[4] = {0,0,0,0}, w1[4] = {0,0,0,0};
#pragma unroll 8
    for (int k = 0; k < 32; k++) {
        float wa = W1s[k * 64 + lane],          wa2 = W1s[k * 64 + 32 + lane];
        float wb = W1s[(64 + k) * 64 + lane],   wb2 = W1s[(64 + k) * 64 + 32 + lane];
        float wg = Wgs[k * 64 + lane],          wg2 = Wgs[k * 64 + 32 + lane];
#pragma unroll
        for (int r = 0; r < 4; r++) {
            float xv = __shfl_sync(FULL, xa[r], k);
            float sv = __shfl_sync(FULL, sa[r], k);
            h0[r] += xv * wa;  h0[r] += sv * wb;
            h1[r] += xv * wa2; h1[r] += sv * wb2;
            w0[r] += sv * wg;  w1[r] += sv * wg2;
        }
    }
#pragma unroll 8
    for (int k = 0; k < 32; k++) {
        int kk = k + 32;
        float wa = W1s[kk * 64 + lane],          wa2 = W1s[kk * 64 + 32 + lane];
        float wb = W1s[(64 + kk) * 64 + lane],   wb2 = W1s[(64 + kk) * 64 + 32 + lane];
        float wg = Wgs[kk * 64 + lane],          wg2 = Wgs[kk * 64 + 32 + lane];
#pragma unroll
        for (int r = 0; r < 4; r++) {
            float xv = __shfl_sync(FULL, xb[r], k);
            float sv = __shfl_sync(FULL, sb[r], k);
            h0[r] += xv * wa;  h0[r] += sv * wb;
            h1[r] += xv * wa2; h1[r] += sv * wb2;
            w0[r] += sv * wg;  w1[r] += sv * wg2;
        }
    }
#pragma unroll
    for (int r = 0; r < 4; r++) {
        int row = r0 + r;
        if (row >= n) break;
        float dvr = g_dinv[row];
        int base = row * 128;
        g_hs[base + lane] = h0[r];        g_hs[base + 32 + lane] = h1[r];
        g_hs[base + 64 + lane] = dvr * w0[r]; g_hs[base + 96 + lane] = dvr * w1[r];
    }
}

// ---------------------------------------------------------------
// Fused layer GEMM (layers 1,2): a = leaky(aggx), t = tanh(aggs + bg_prev)
// hw = a@M + t@W1b ; sws = dinv*(t@Wg). Interleaved store.
__global__ void k1_fused(const float* __restrict__ M, const float* __restrict__ W1b,
                         const float* __restrict__ Wg, const float* __restrict__ bgp, int n) {
    __shared__ float Ms[64 * 64];
    __shared__ float Bs[64 * 64];
    __shared__ float Gs[64 * 64];
    int tid = threadIdx.x;
    for (int i = tid; i < 64 * 64; i += 256) { Ms[i] = M[i]; Bs[i] = W1b[i]; Gs[i] = Wg[i]; }
    __syncthreads();
    int lane = tid & 31;
    int warp = blockIdx.x * 8 + (tid >> 5);
    int r0 = warp * 4;
    if (r0 >= n) return;

    float b0v = bgp[lane], b1v = bgp[32 + lane];
    float aa[4], ab[4], ta[4], tb[4];
#pragma unroll
    for (int r = 0; r < 4; r++) {
        int row = min(r0 + r, n - 1);
        float v0 = g_aggx[row * 64 + lane], v1 = g_aggx[row * 64 + 32 + lane];
        aa[r] = v0 > 0.f ? v0 : 0.01f * v0;
        ab[r] = v1 > 0.f ? v1 : 0.01f * v1;
        ta[r] = tanhf(g_aggs[row * 64 + lane] + b0v);
        tb[r] = tanhf(g_aggs[row * 64 + 32 + lane] + b1v);
    }
    float h0[4] = {0,0,0,0}, h1[4] = {0,0,0,0}, w0[4] = {0,0,0,0}, w1[4] = {0,0,0,0};
#pragma unroll 8
    for (int k = 0; k < 32; k++) {
        float wa = Ms[k * 64 + lane], wa2 = Ms[k * 64 + 32 + lane];
        float wb = Bs[k * 64 + lane], wb2 = Bs[k * 64 + 32 + lane];
        float wg = Gs[k * 64 + lane], wg2 = Gs[k * 64 + 32 + lane];
#pragma unroll
        for (int r = 0; r < 4; r++) {
            float av = __shfl_sync(FULL, aa[r], k);
            float tv = __shfl_sync(FULL, ta[r], k);
            h0[r] += av * wa;  h0[r] += tv * wb;
            h1[r] += av * wa2; h1[r] += tv * wb2;
            w0[r] += tv * wg;  w1[r] += tv * wg2;
        }
    }
#pragma unroll 8
    for (int k = 0; k < 32; k++) {
        int kk = k + 32;
        float wa = Ms[kk * 64 + lane], wa2 = Ms[kk * 64 + 32 + lane];
        float wb = Bs[kk * 64 + lane], wb2 = Bs[kk * 64 + 32 + lane];
        float wg = Gs[kk * 64 + lane], wg2 = Gs[kk * 64 + 32 + lane];
#pragma unroll
        for (int r = 0; r < 4; r++) {
            float av = __shfl_sync(FULL, ab[r], k);
            float tv = __shfl_sync(FULL, tb[r], k);
            h0[r] += av * wa;  h0[r] += tv * wb;
            h1[r] += av * wa2; h1[r] += tv * wb2;
            w0[r] += tv * wg;  w1[r] += tv * wg2;
        }
    }
#pragma unroll
    for (int r = 0; r < 4; r++) {
        int row = r0 + r;
        if (row >= n) break;
        float dvr = g_dinv[row];
        int base = row * 128;
        g_hs[base + lane] = h0[r];        g_hs[base + 32 + lane] = h1[r];
        g_hs[base + 64 + lane] = dvr * w0[r]; g_hs[base + 96 + lane] = dvr * w1[r];
    }
}

// ---------------------------------------------------------------
// CSR gather: warp per dst node; each lane one float4 of the 512B node row.
__global__ void k_gather(int n) {
    int di = blockIdx.x * 8 + (threadIdx.x >> 5);
    if (di >= n) return;
    int lane = threadIdx.x & 31;
    const float4* hs = (const float4*)g_hs;
    float4 acc = hs[di * 32 + lane];            // self term
    int beg = g_rowstart[di], end = g_rowstart[di + 1];
    int j = beg;
    for (; j + 4 <= end; j += 4) {
        int s0 = g_csr[j], s1 = g_csr[j + 1], s2 = g_csr[j + 2], s3 = g_csr[j + 3];
        float4 v0 = hs[s0 * 32 + lane];
        float4 v1 = hs[s1 * 32 + lane];
        float4 v2 = hs[s2 * 32 + lane];
        float4 v3 = hs[s3 * 32 + lane];
        acc.x += v0.x + v1.x + v2.x + v3.x;
        acc.y += v0.y + v1.y + v2.y + v3.y;
        acc.z += v0.z + v1.z + v2.z + v3.z;
        acc.w += v0.w + v1.w + v2.w + v3.w;
    }
    for (; j < end; j++) {
        float4 v = hs[g_csr[j] * 32 + lane];
        acc.x += v.x; acc.y += v.y; acc.z += v.z; acc.w += v.w;
    }
    if (lane < 16) {
        ((float4*)g_aggx)[di * 16 + lane] = acc;
    } else {
        float dv = g_dinv[di];
        acc.x *= dv; acc.y *= dv; acc.z *= dv; acc.w *= dv;
        ((float4*)g_aggs)[di * 16 + lane - 16] = acc;
    }
}

// ---------------------------------------------------------------
// FAST TAIL (pooled-only): one pass over aggx/aggs.
__global__ void k_tail(const float* __restrict__ bg, int n, int G) {
    __shared__ float la_s[128 * 64];   // 32KB
    int tid = threadIdx.x;
    int c = tid & 63, q = tid >> 6;
    int r0 = blockIdx.x * 128;
    float bgc = bg[c];
    float accL = 0.f, accT = 0.f, cntRun = 0.f;
    int curg = -1;
    for (int rr = q; rr < 128; rr += 4) {
        int r = r0 + rr;
        if (r < n) {
            float v = g_aggx[r * 64 + c];
            float la = v > 0.f ? v : 0.01f * v;
            la_s[rr * 64 + c] = la;
            float tv = tanhf(g_aggs[r * 64 + c] + bgc);
            int g = g_batch[r];
            if ((unsigned)g >= (unsigned)G) g = 0;
            if (g != curg) {
                if (curg >= 0) {
                    atomicAdd(&g_Sla[curg * 64 + c], accL);
                    atomicAdd(&g_St[curg * 64 + c], accT);
                    if (c == 0) atomicAdd(&g_cntf[curg], cntRun);
                }
                curg = g; accL = 0.f; accT = 0.f; cntRun = 0.f;
            }
            accL += la; accT += tv; cntRun += 1.f;
        } else {
            la_s[rr * 64 + c] = 0.f;
        }
    }
    if (curg >= 0) {
        atomicAdd(&g_Sla[curg * 64 + c], accL);
        atomicAdd(&g_St[curg * 64 + c], accT);
        if (c == 0) atomicAdd(&g_cntf[curg], cntRun);
    }
    __syncthreads();
    // covariance: thread computes a 4x4 tile of C
    int a0 = (tid >> 4) * 4, b0 = (tid & 15) * 4;
    float C00=0,C01=0,C02=0,C03=0, C10=0,C11=0,C12=0,C13=0;
    float C20=0,C21=0,C22=0,C23=0, C30=0,C31=0,C32=0,C33=0;
    for (int r = 0; r < 128; r++) {
        float4 va = *(const float4*)&la_s[r * 64 + a0];
        float4 vb = *(const float4*)&la_s[r * 64 + b0];
        C00 += va.x*vb.x; C01 += va.x*vb.y; C02 += va.x*vb.z; C03 += va.x*vb.w;
        C10 += va.y*vb.x; C11 += va.y*vb.y; C12 += va.y*vb.z; C13 += va.y*vb.w;
        C20 += va.z*vb.x; C21 += va.z*vb.y; C22 += va.z*vb.z; C23 += va.z*vb.w;
        C30 += va.w*vb.x; C31 += va.w*vb.y; C32 += va.w*vb.z; C33 += va.w*vb.w;
    }
    atomicAdd(&g_C[(a0+0)*64+b0+0], C00); atomicAdd(&g_C[(a0+0)*64+b0+1], C01);
    atomicAdd(&g_C[(a0+0)*64+b0+2], C02); atomicAdd(&g_C[(a0+0)*64+b0+3], C03);
    atomicAdd(&g_C[(a0+1)*64+b0+0], C10); atomicAdd(&g_C[(a0+1)*64+b0+1], C11);
    atomicAdd(&g_C[(a0+1)*64+b0+2], C12); atomicAdd(&g_C[(a0+1)*64+b0+3], C13);
    atomicAdd(&g_C[(a0+2)*64+b0+0], C20); atomicAdd(&g_C[(a0+2)*64+b0+1], C21);
    atomicAdd(&g_C[(a0+2)*64+b0+2], C22); atomicAdd(&g_C[(a0+2)*64+b0+3], C23);
    atomicAdd(&g_C[(a0+3)*64+b0+0], C30); atomicAdd(&g_C[(a0+3)*64+b0+1], C31);
    atomicAdd(&g_C[(a0+3)*64+b0+2], C32); atomicAdd(&g_C[(a0+3)*64+b0+3], C33);
}

// BN stats from covariance
__global__ void k_bn2(const float* __restrict__ W2, int n, int G) {
    __shared__ float Cs[4096];
    __shared__ float W2s[4096];
    __shared__ float qpart[256];
    __shared__ float Tla[64];
    int tid = threadIdx.x;
    for (int i = tid; i < 4096; i += 256) { Cs[i] = g_C[i]; W2s[i] = W2[i]; }
    __syncthreads();
    int c = tid & 63, p = tid >> 6;
    float part = 0.f;
    for (int r = p; r < 64; r += 4) {
        float inner = 0.f;
#pragma unroll 16
        for (int k = 0; k < 64; k++) inner = fmaf(Cs[r * 64 + k], W2s[k * 64 + c], inner);
        part = fmaf(W2s[r * 64 + c], inner, part);
    }
    qpart[tid] = part;
    if (tid < 64) {
        float t = 0.f;
        for (int g = 0; g < G; g++) t += g_Sla[g * 64 + tid];
        Tla[tid] = t;
    }
    __syncthreads();
    if (tid < 64) {
        float quad = qpart[tid] + qpart[64 + tid] + qpart[128 + tid] + qpart[192 + tid];
        float mean = 0.f;
#pragma unroll 16
        for (int k = 0; k < 64; k++) mean = fmaf(Tla[k], W2s[k * 64 + tid], mean);
        mean /= (float)n;
        float var = quad / (float)n - mean * mean;
        g_stats[tid] = mean;
        g_stats[64 + tid] = rsqrtf(var + 1e-4f);
    }
}

__global__ void k_pool(const float* __restrict__ W2, const float* __restrict__ gamma,
                       const float* __restrict__ beta, const float* __restrict__ Wh,
                       const float* __restrict__ bh, float* __restrict__ pooled) {
    __shared__ float Sl[64], Stm[64], xls[64];
    int g = blockIdx.x;
    int c = threadIdx.x;
    Sl[c] = g_Sla[g * 64 + c];
    Stm[c] = g_St[g * 64 + c];
    float cnt = g_cntf[g];
    __syncthreads();
    float sx3 = 0.f;
#pragma unroll 16
    for (int k = 0; k < 64; k++) sx3 = fmaf(Sl[k], W2[k * 64 + c], sx3);
    float m = g_stats[c], iv = g_stats[64 + c];
    xls[c] = gamma[c] * iv * (sx3 - cnt * m) + cnt * beta[c];
    __syncthreads();
    float o = cnt * bh[c];
#pragma unroll 16
    for (int k = 0; k < 64; k++) o = fmaf(xls[k], Wh[k * 64 + c], o);
#pragma unroll 16
    for (int k = 0; k < 64; k++) o = fmaf(Stm[k], Wh[(64 + k) * 64 + c], o);
    pooled[g * 64 + c] = o;
}

// ---------------------------------------------------------------
// FALLBACK PATH (x_local output required)
__global__ void k3_mlp(const float* __restrict__ W2, const float* __restrict__ bg, int n) {
    __shared__ float Ws[64 * 64];
    __shared__ float shst[128];
    int tid = threadIdx.x;
    for (int i = tid; i < 64 * 64; i += 256) Ws[i] = W2[i];
    if (tid < 128) shst[tid] = 0.f;
    __syncthreads();
    int lane = tid & 31;
    int warp = blockIdx.x * 8 + (tid >> 5);
    int r0 = warp * 4;
    bool active = (r0 < n);
    float sum0 = 0.f, sum1 = 0.f, sq0 = 0.f, sq1 = 0.f;
    if (active) {
        float a0[4], a1[4];
#pragma unroll
        for (int r = 0; r < 4; r++) {
            int row = min(r0 + r, n - 1);
            float v0 = g_aggx[row * 64 + lane], v1 = g_aggx[row * 64 + 32 + lane];
            a0[r] = v0 > 0.f ? v0 : 0.01f * v0;
            a1[r] = v1 > 0.f ? v1 : 0.01f * v1;
        }
        float o0[4] = {0,0,0,0}, o1[4] = {0,0,0,0};
#pragma unroll 8
        for (int k = 0; k < 32; k++) {
            float w = Ws[k * 64 + lane], w2 = Ws[k * 64 + 32 + lane];
#pragma unroll
            for (int r = 0; r < 4; r++) {
                float xv = __shfl_sync(FULL, a0[r], k);
                o0[r] += xv * w; o1[r] += xv * w2;
            }
        }
#pragma unroll 8
        for (int k = 0; k < 32; k++) {
            int kk = k + 32;
            float w = Ws[kk * 64 + lane], w2 = Ws[kk * 64 + 32 + lane];
#pragma unroll
            for (int r = 0; r < 4; r++) {
                float xv = __shfl_sync(FULL, a1[r], k);
                o0[r] += xv * w; o1[r] += xv * w2;
            }
        }
        float b0 = bg[lane], b1 = bg[32 + lane];
#pragma unroll
        for (int r = 0; r < 4; r++) {
            int row = r0 + r;
            if (row >= n) break;
            g_x[row * 64 + lane] = o0[r]; g_x[row * 64 + 32 + lane] = o1[r];
            g_s[row * 64 + lane]      = tanhf(g_aggs[row * 64 + lane] + b0);
            g_s[row * 64 + 32 + lane] = tanhf(g_aggs[row * 64 + 32 + lane] + b1);
            sum0 += o0[r]; sq0 += o0[r] * o0[r];
            sum1 += o1[r]; sq1 += o1[r] * o1[r];
        }
    }
    atomicAdd(&shst[lane], sum0);
    atomicAdd(&shst[32 + lane], sum1);
    atomicAdd(&shst[64 + lane], sq0);
    atomicAdd(&shst[96 + lane], sq1);
    __syncthreads();
    if (tid < 128) atomicAdd(&g_stats[tid], shst[tid]);
}

__global__ void k_bn(int n) {
    int c = threadIdx.x;
    float mean = g_stats[c] / (float)n;
    float var = g_stats[64 + c] / (float)n - mean * mean;
    g_stats[c] = mean;
    g_stats[64 + c] = rsqrtf(var + 1e-4f);
}

__global__ void k_final(const float* __restrict__ gamma, const float* __restrict__ beta,
                        const float* __restrict__ Wh, const float* __restrict__ bh,
                        float* __restrict__ pooled, float* __restrict__ xl_out,
                        int n, int G) {
    __shared__ float Ws[128 * 64];
    int tid = threadIdx.x;
    for (int i = tid; i < 128 * 64; i += 256) Ws[i] = Wh[i];
    __syncthreads();
    int lane = tid & 31;
    int warp = blockIdx.x * 8 + (tid >> 5);
    int r0 = warp * 4;
    if (r0 >= n) return;
    float m0 = g_stats[lane],      m1 = g_stats[32 + lane];
    float i0 = g_stats[64 + lane], i1 = g_stats[96 + lane];
    float ga0 = gamma[lane], ga1 = gamma[32 + lane];
    float be0 = beta[lane],  be1 = beta[32 + lane];
    float xl0[4], xl1[4], sv0[4], sv1[4];
    int bidx[4];
#pragma unroll
    for (int r = 0; r < 4; r++) {
        int row = min(r0 + r, n - 1);
        xl0[r] = ga0 * (g_x[row * 64 + lane] - m0) * i0 + be0;
        xl1[r] = ga1 * (g_x[row * 64 + 32 + lane] - m1) * i1 + be1;
        sv0[r] = g_s[row * 64 + lane];
        sv1[r] = g_s[row * 64 + 32 + lane];
        int b = g_batch[row];
        bidx[r] = ((unsigned)b < (unsigned)G) ? b : 0;
    }
    float bh0 = bh[lane], bh1 = bh[32 + lane];
    float o0[4], o1[4];
#pragma unroll
    for (int r = 0; r < 4; r++) { o0[r] = bh0; o1[r] = bh1; }
#pragma unroll 8
    for (int k = 0; k < 32; k++) {
        float w = Ws[k * 64 + lane], w2 = Ws[k * 64 + 32 + lane];
#pragma unroll
        for (int r = 0; r < 4; r++) { float v = __shfl_sync(FULL, xl0[r], k); o0[r] += v * w; o1[r] += v * w2; }
    }
#pragma unroll 8
    for (int k = 0; k < 32; k++) {
        int kk = 32 + k;
        float w = Ws[kk * 64 + lane], w2 = Ws[kk * 64 + 32 + lane];
#pragma unroll
        for (int r = 0; r < 4; r++) { float v = __shfl_sync(FULL, xl1[r], k); o0[r] += v * w; o1[r] += v * w2; }
    }
#pragma unroll 8
    for (int k = 0; k < 32; k++) {
        int kk = 64 + k;
        float w = Ws[kk * 64 + lane], w2 = Ws[kk * 64 + 32 + lane];
#pragma unroll
        for (int r = 0; r < 4; r++) { float v = __shfl_sync(FULL, sv0[r], k); o0[r] += v * w; o1[r] += v * w2; }
    }
#pragma unroll 8
    for (int k = 0; k < 32; k++) {
        int kk = 96 + k;
        float w = Ws[kk * 64 + lane], w2 = Ws[kk * 64 + 32 + lane];
#pragma unroll
        for (int r = 0; r < 4; r++) { float v = __shfl_sync(FULL, sv1[r], k); o0[r] += v * w; o1[r] += v * w2; }
    }
    if (xl_out) {
#pragma unroll
        for (int r = 0; r < 4; r++) {
            int row = r0 + r;
            if (row >= n) break;
            xl_out[row * 64 + lane] = xl0[r];
            xl_out[row * 64 + 32 + lane] = xl1[r];
        }
    }
    int nvalid = min(n - r0, 4);
    for (int r = 0; r < nvalid; r++) {
        atomicAdd(&pooled[bidx[r] * 64 + lane], o0[r]);
        atomicAdd(&pooled[bidx[r] * 64 + 32 + lane], o1[r]);
    }
}

// ---------------------------------------------------------------
extern "C" void kernel_launch(void* const* d_in, const int* in_sizes, int n_in,
                              void* d_out, int out_size) {
    int ix, is_, iW1, iW2, iGa, iBe, iWg, iBg, iWh, iBh, iEi, iBa;
    if (n_in >= 2 && in_sizes[0] == in_sizes[1]) {
        ix = 0; is_ = 1; iW1 = 2; iW2 = 3; iGa = 4; iBe = 5;
        iWg = 6; iBg = 7; iWh = 8; iBh = 9; iEi = 10; iBa = 11;
    } else {
        iW1 = 0; iW2 = 1; iWg = 2; iWh = 3; iBa = 4; iBe = 5;
        iBg = 6; iBh = 7; iEi = 8; iGa = 9; is_ = 10; ix = 11;
    }

    const float* x     = (const float*)d_in[ix];
    const float* s     = (const float*)d_in[is_];
    const float* W1    = (const float*)d_in[iW1];
    const float* W2    = (const float*)d_in[iW2];
    const float* gamma = (const float*)d_in[iGa];
    const float* beta  = (const float*)d_in[iBe];
    const float* Wg    = (const float*)d_in[iWg];
    const float* bg    = (const float*)d_in[iBg];
    const float* Wh    = (const float*)d_in[iWh];
    const float* bh    = (const float*)d_in[iBh];
    const int* eraw    = (const int*)d_in[iEi];
    const int* braw    = (const int*)d_in[iBa];
    float* out = (float*)d_out;

    int n = in_sizes[ix] / 64;
    int E = in_sizes[iEi] / 2;
    if (n > MAXN) n = MAXN;
    if (E > MAXE) E = MAXE;

    // ---- output layout resolution ----
    float* pooledPtr;
    float* xlocalPtr;
    int G;
    float* gpool;
    cudaGetSymbolAddress((void**)&gpool, g_pooled);
    if (out_size > n * 64) {
        G = out_size / 64 - n;
        pooledPtr = out;
        xlocalPtr = out + (long)G * 64;
    } else if (out_size == n * 64) {
        G = 64;
        pooledPtr = gpool;
        xlocalPtr = out;
    } else {
        G = out_size / 64;
        pooledPtr = out;
        xlocalPtr = nullptr;
    }
    if (G > MAXG) G = MAXG;
    if (G < 1) G = 1;

    int gemmBlocks = (((n + 3) / 4) + 7) / 8;
    int nodeBlocks = (n + 7) / 8;
    int cvtBlocks = ((E > n ? E : n) + 255) / 256;
    int scanBlocks = (n + SCAN_ELEMS - 1) / SCAN_ELEMS;
    float* d_M;
    cudaGetSymbolAddress((void**)&d_M, g_M);

    // setup
    k_detect<<<1, 256>>>(eraw, 2 * E);
    k_zero<<<(n + 255) / 256, 256>>>(pooledPtr, n, G);
    k_convert<<<cvtBlocks, 256>>>(eraw, braw, E, n);
    k_scan1<<<scanBlocks, SCAN_BLOCK>>>(n);
    k_scan2<<<1, 64>>>(scanBlocks, n);
    k_scan3<<<scanBlocks, SCAN_BLOCK>>>(n);
    k_fill<<<(E + 255) / 256, 256>>>(E);
    k_precompute<<<128, 64>>>(W1, W2);

    // layer 0
    k1_gemm<<<gemmBlocks, 256>>>(x, s, W1, Wg, n);
    k_gather<<<nodeBlocks, 256>>>(n);
    // layer 1 (fused with layer-0 MLP second linear)
    k1_fused<<<gemmBlocks, 256>>>(d_M, W1 + 1 * 128 * 64 + 64 * 64, Wg + 1 * 64 * 64, bg, n);
    k_gather<<<nodeBlocks, 256>>>(n);
    // layer 2
    k1_fused<<<gemmBlocks, 256>>>(d_M + 4096, W1 + 2 * 128 * 64 + 64 * 64, Wg + 2 * 64 * 64, bg + 64, n);
    k_gather<<<nodeBlocks, 256>>>(n);

    if (xlocalPtr == nullptr) {
        // FAST TAIL: pooled-only, x3/s never materialized
        k_tail<<<(n + 127) / 128, 256>>>(bg + 2 * 64, n, G);
        k_bn2<<<1, 256>>>(W2 + 2 * 64 * 64, n, G);
        k_pool<<<G, 64>>>(W2 + 2 * 64 * 64, gamma + 2 * 64, beta + 2 * 64, Wh, bh, pooledPtr);
    } else {
        // fallback: x_local required
        k3_mlp<<<gemmBlocks, 256>>>(W2 + 2 * 64 * 64, bg + 2 * 64, n);
        k_bn<<<1, 64>>>(n);
        k_final<<<gemmBlocks, 256>>>(gamma + 2 * 64, beta + 2 * 64, Wh, bh,
                                     pooledPtr, xlocalPtr, n, G);
    }
}

// round 13
// speedup vs baseline: 1.5709x; 1.0590x over previous
#include <cuda_runtime.h>
#include <cuda_fp16.h>
#include <math.h>

#define FULL 0xffffffffu
constexpr int D = 64;
constexpr int MAXN = 50048;
constexpr int MAXE = 800000;
constexpr int MAXG = 128;
constexpr int SCAN_CHUNK = 16;
constexpr int SCAN_BLOCK = 256;
constexpr int SCAN_ELEMS = SCAN_BLOCK * SCAN_CHUNK;   // 4096 per block

// ---- scratch (no allocations allowed) ----
__device__ float g_x[MAXN * D];
__device__ float g_s[MAXN * D];
__device__ __half2 g_hs2[MAXN * D];    // per node: 64 half2 = [hw cols 0..63 | dinv*sw cols 0..63]
__device__ float g_aggx[MAXN * D];
__device__ float g_aggs[MAXN * D];
__device__ float g_dinv[MAXN];
__device__ float g_stats[2 * D];
__device__ float g_pooled[MAXG * D];
__device__ float g_M[2 * D * D];       // W2_l @ W1_{l+1}[0:64,:]
__device__ float g_Sla[MAXG * D];
__device__ float g_St[MAXG * D];
__device__ float g_C[D * D];
__device__ float g_cntf[MAXG];
__device__ int g_src[MAXE];
__device__ int g_dst[MAXE];
__device__ int g_csr[MAXE];
__device__ int g_batch[MAXN];
__device__ int g_degi[MAXN];
__device__ int g_rowstart[MAXN + 1];
__device__ int g_cursor[MAXN];
__device__ int g_blocksum[64];
__device__ int g_blockoff[64];
__device__ int g_is64;

// ---------------------------------------------------------------
__global__ void k_detect(const int* __restrict__ eraw, int totalInts) {
    __shared__ int anyNZ;
    if (threadIdx.x == 0) anyNZ = 0;
    __syncthreads();
    int limit = min(totalInts, 4096);
    for (int i = threadIdx.x * 2 + 1; i < limit; i += 512)
        if (eraw[i] != 0) anyNZ = 1;
    __syncthreads();
    if (threadIdx.x == 0) g_is64 = anyNZ ? 0 : 1;
}

__global__ void k_zero(float* pooled, int n, int G) {
    int i = blockIdx.x * blockDim.x + threadIdx.x;
    if (i < n) g_degi[i] = 0;
    if (i < 2 * D) g_stats[i] = 0.f;
    if (i < G * D) pooled[i] = 0.f;
    if (i < MAXG * D) { g_Sla[i] = 0.f; g_St[i] = 0.f; }
    if (i < D * D) g_C[i] = 0.f;
    if (i < MAXG) g_cntf[i] = 0.f;
}

// convert indices (+ degree histogram fused in)
__global__ void k_convert(const int* __restrict__ eraw, const int* __restrict__ braw,
                          int E, int n) {
    int i = blockIdx.x * blockDim.x + threadIdx.x;
    bool is64 = (g_is64 != 0);
    if (i < E) {
        int sv = is64 ? eraw[2 * i] : eraw[i];
        int dv = is64 ? eraw[2 * (E + i)] : eraw[E + i];
        if ((unsigned)sv >= (unsigned)n) sv = 0;
        if ((unsigned)dv >= (unsigned)n) dv = 0;
        g_src[i] = sv;
        g_dst[i] = dv;
        atomicAdd(&g_degi[dv], 1);
    }
    if (i < n) g_batch[i] = is64 ? braw[2 * i] : braw[i];
}

// ---------------------------------------------------------------
// 3-phase parallel exclusive scan over g_degi -> rowstart/cursor/dinv
__global__ void k_scan1(int n) {
    __shared__ int ts[SCAN_BLOCK];
    int t = threadIdx.x, b = blockIdx.x;
    int base = b * SCAN_ELEMS + t * SCAN_CHUNK;
    int sum = 0;
#pragma unroll
    for (int i = 0; i < SCAN_CHUNK; i++) {
        int idx = base + i;
        if (idx < n) sum += g_degi[idx];
    }
    ts[t] = sum;
    __syncthreads();
    for (int off = 128; off > 0; off >>= 1) {
        if (t < off) ts[t] += ts[t + off];
        __syncthreads();
    }
    if (t == 0) g_blocksum[b] = ts[0];
}

__global__ void k_scan2(int nb, int n) {
    __shared__ int sh[64];
    int t = threadIdx.x;   // 64 threads
    int v = (t < nb) ? g_blocksum[t] : 0;
    sh[t] = v;
    __syncthreads();
    for (int off = 1; off < 64; off <<= 1) {
        int vv = (t >= off) ? sh[t - off] : 0;
        __syncthreads();
        sh[t] += vv;
        __syncthreads();
    }
    if (t < nb) g_blockoff[t] = sh[t] - v;   // exclusive
    if (t == 63) g_rowstart[n] = sh[63];     // total
}

__global__ void k_scan3(int n) {
    __shared__ int ts[SCAN_BLOCK];
    int t = threadIdx.x, b = blockIdx.x;
    int base = b * SCAN_ELEMS + t * SCAN_CHUNK;
    int deg[SCAN_CHUNK];
    int sum = 0;
#pragma unroll
    for (int i = 0; i < SCAN_CHUNK; i++) {
        int idx = base + i;
        deg[i] = (idx < n) ? g_degi[idx] : 0;
        sum += deg[i];
    }
    ts[t] = sum;
    __syncthreads();
    for (int off = 1; off < SCAN_BLOCK; off <<= 1) {
        int v = (t >= off) ? ts[t - off] : 0;
        __syncthreads();
        ts[t] += v;
        __syncthreads();
    }
    int run = g_blockoff[b] + ts[t] - sum;   // exclusive start for this thread
#pragma unroll
    for (int i = 0; i < SCAN_CHUNK; i++) {
        int idx = base + i;
        if (idx < n) {
            g_rowstart[idx] = run;
            g_cursor[idx] = run;
            g_dinv[idx] = rsqrtf((float)deg[i] + 1.0f);
            run += deg[i];
        }
    }
}

__global__ void k_fill(int E) {
    int e = blockIdx.x * blockDim.x + threadIdx.x;
    if (e < E) {
        int pos = atomicAdd(&g_cursor[g_dst[e]], 1);
        g_csr[pos] = g_src[e];
    }
}

// ---------------------------------------------------------------
// M[l] = W2_l @ W1_{l+1}[0:64,:]
__global__ void k_precompute(const float* __restrict__ W1, const float* __restrict__ W2) {
    int b = blockIdx.x;
    int l = b >> 6, k = b & 63;
    int c = threadIdx.x;
    const float* W2l = W2 + l * 4096;
    const float* W1a = W1 + (l + 1) * 8192;
    float acc = 0.f;
#pragma unroll 16
    for (int j = 0; j < 64; j++) acc = fmaf(W2l[k * 64 + j], W1a[j * 64 + c], acc);
    g_M[l * 4096 + k * 64 + c] = acc;
}

// ---------------------------------------------------------------
// Layer-0 GEMM: hw = x@W1a + s@W1b ; sws = dinv*(s@Wg).
// Lane computes adjacent cols (2l, 2l+1); packs half2; interleaved store.
__global__ void k1_gemm(const float* __restrict__ xin, const float* __restrict__ sin,
                        const float* __restrict__ W1, const float* __restrict__ Wg, int n) {
    __shared__ float W1s[128 * 64];
    __shared__ float Wgs[64 * 64];
    int tid = threadIdx.x;
    for (int i = tid; i < 128 * 64; i += 256) W1s[i] = W1[i];
    for (int i = tid; i < 64 * 64; i += 256) Wgs[i] = Wg[i];
    __syncthreads();
    int lane = tid & 31;
    int warp = blockIdx.x * 8 + (tid >> 5);
    int r0 = warp * 4;
    if (r0 >= n) return;

    const float2* W1p = (const float2*)W1s;
    const float2* Wgp = (const float2*)Wgs;

    float xa[4], xb[4], sa[4], sb[4];
#pragma unroll
    for (int r = 0; r < 4; r++) {
        int row = min(r0 + r, n - 1);
        xa[r] = xin[row * 64 + lane];  xb[r] = xin[row * 64 + 32 + lane];
        sa[r] = sin[row * 64 + lane];  sb[r] = sin[row * 64 + 32 + lane];
    }
    float h0[4] = {0,0,0,0}, h1[4] = {0,0,0,0}, w0[4] = {0,0,0,0}, w1[4] = {0,0,0,0};
#pragma unroll 8
    for (int k = 0; k < 32; k++) {
        float2 wa = W1p[k * 32 + lane];
        float2 wb = W1p[(64 + k) * 32 + lane];
        float2 wg = Wgp[k * 32 + lane];
#pragma unroll
        for (int r = 0; r < 4; r++) {
            float xv = __shfl_sync(FULL, xa[r], k);
            float sv = __shfl_sync(FULL, sa[r], k);
            h0[r] += xv * wa.x;  h0[r] += sv * wb.x;
            h1[r] += xv * wa.y;  h1[r] += sv * wb.y;
            w0[r] += sv * wg.x;  w1[r] += sv * wg.y;
        }
    }
#pragma unroll 8
    for (int k = 0; k < 32; k++) {
        int kk = k + 32;
        float2 wa = W1p[kk * 32 + lane];
        float2 wb = W1p[(64 + kk) * 32 + lane];
        float2 wg = Wgp[kk * 32 + lane];
#pragma unroll
        for (int r = 0; r < 4; r++) {
            float xv = __shfl_sync(FULL, xb[r], k);
            float sv = __shfl_sync(FULL, sb[r], k);
            h0[r] += xv * wa.x;  h0[r] += sv * wb.x;
            h1[r] += xv * wa.y;  h1[r] += sv * wb.y;
            w0[r] += sv * wg.x;  w1[r] += sv * wg.y;
        }
    }
#pragma unroll
    for (int r = 0; r < 4; r++) {
        int row = r0 + r;
        if (row >= n) break;
        float dvr = g_dinv[row];
        g_hs2[row * 64 + lane]      = __floats2half2_rn(h0[r], h1[r]);
        g_hs2[row * 64 + 32 + lane] = __floats2half2_rn(dvr * w0[r], dvr * w1[r]);
    }
}

// ---------------------------------------------------------------
// Fused layer GEMM (layers 1,2): a = leaky(aggx), t = tanh(aggs + bg_prev)
// hw = a@M + t@W1b ; sws = dinv*(t@Wg). half2 interleaved store.
__global__ void k1_fused(const float* __restrict__ M, const float* __restrict__ W1b,
                         const float* __restrict__ Wg, const float* __restrict__ bgp, int n) {
    __shared__ float Ms[64 * 64];
    __shared__ float Bs[64 * 64];
    __shared__ float Gs[64 * 64];
    int tid = threadIdx.x;
    for (int i = tid; i < 64 * 64; i += 256) { Ms[i] = M[i]; Bs[i] = W1b[i]; Gs[i] = Wg[i]; }
    __syncthreads();
    int lane = tid & 31;
    int warp = blockIdx.x * 8 + (tid >> 5);
    int r0 = warp * 4;
    if (r0 >= n) return;

    const float2* Mp = (const float2*)Ms;
    const float2* Bp = (const float2*)Bs;
    const float2* Gp = (const float2*)Gs;

    float b0v = bgp[lane], b1v = bgp[32 + lane];
    float aa[4], ab[4], ta[4], tb[4];
#pragma unroll
    for (int r = 0; r < 4; r++) {
        int row = min(r0 + r, n - 1);
        float v0 = g_aggx[row * 64 + lane], v1 = g_aggx[row * 64 + 32 + lane];
        aa[r] = v0 > 0.f ? v0 : 0.01f * v0;
        ab[r] = v1 > 0.f ? v1 : 0.01f * v1;
        ta[r] = tanhf(g_aggs[row * 64 + lane] + b0v);
        tb[r] = tanhf(g_aggs[row * 64 + 32 + lane] + b1v);
    }
    float h0[4] = {0,0,0,0}, h1[4] = {0,0,0,0}, w0[4] = {0,0,0,0}, w1[4] = {0,0,0,0};
#pragma unroll 8
    for (int k = 0; k < 32; k++) {
        float2 wa = Mp[k * 32 + lane];
        float2 wb = Bp[k * 32 + lane];
        float2 wg = Gp[k * 32 + lane];
#pragma unroll
        for (int r = 0; r < 4; r++) {
            float av = __shfl_sync(FULL, aa[r], k);
            float tv = __shfl_sync(FULL, ta[r], k);
            h0[r] += av * wa.x;  h0[r] += tv * wb.x;
            h1[r] += av * wa.y;  h1[r] += tv * wb.y;
            w0[r] += tv * wg.x;  w1[r] += tv * wg.y;
        }
    }
#pragma unroll 8
    for (int k = 0; k < 32; k++) {
        int kk = k + 32;
        float2 wa = Mp[kk * 32 + lane];
        float2 wb = Bp[kk * 32 + lane];
        float2 wg = Gp[kk * 32 + lane];
#pragma unroll
        for (int r = 0; r < 4; r++) {
            float av = __shfl_sync(FULL, ab[r], k);
            float tv = __shfl_sync(FULL, tb[r], k);
            h0[r] += av * wa.x;  h0[r] += tv * wb.x;
            h1[r] += av * wa.y;  h1[r] += tv * wb.y;
            w0[r] += tv * wg.x;  w1[r] += tv * wg.y;
        }
    }
#pragma unroll
    for (int r = 0; r < 4; r++) {
        int row = r0 + r;
        if (row >= n) break;
        float dvr = g_dinv[row];
        g_hs2[row * 64 + lane]      = __floats2half2_rn(h0[r], h1[r]);
        g_hs2[row * 64 + 32 + lane] = __floats2half2_rn(dvr * w0[r], dvr * w1[r]);
    }
}

// ---------------------------------------------------------------
// CSR gather: warp per dst node; lane accumulates cols (2l,2l+1) of hw AND sws.
// Per neighbor: 2 coalesced half2 loads (256B/warp). fp32 accumulation.
__global__ void k_gather(int n) {
    int di = blockIdx.x * 8 + (threadIdx.x >> 5);
    if (di >= n) return;
    int lane = threadIdx.x & 31;
    const __half2* hs = g_hs2;
    // self term
    float2 hx = __half22float2(hs[di * 64 + lane]);
    float2 hw = __half22float2(hs[di * 64 + 32 + lane]);
    float ax0 = hx.x, ax1 = hx.y;
    float as0 = hw.x, as1 = hw.y;
    int beg = g_rowstart[di], end = g_rowstart[di + 1];
    int j = beg;
    for (; j + 4 <= end; j += 4) {
        int s0 = g_csr[j], s1 = g_csr[j + 1], s2 = g_csr[j + 2], s3 = g_csr[j + 3];
        __half2 a0 = hs[s0 * 64 + lane], b0 = hs[s0 * 64 + 32 + lane];
        __half2 a1 = hs[s1 * 64 + lane], b1 = hs[s1 * 64 + 32 + lane];
        __half2 a2 = hs[s2 * 64 + lane], b2 = hs[s2 * 64 + 32 + lane];
        __half2 a3 = hs[s3 * 64 + lane], b3 = hs[s3 * 64 + 32 + lane];
        float2 f0 = __half22float2(a0), g0 = __half22float2(b0);
        float2 f1 = __half22float2(a1), g1 = __half22float2(b1);
        float2 f2 = __half22float2(a2), g2 = __half22float2(b2);
        float2 f3 = __half22float2(a3), g3 = __half22float2(b3);
        ax0 += f0.x + f1.x + f2.x + f3.x;
        ax1 += f0.y + f1.y + f2.y + f3.y;
        as0 += g0.x + g1.x + g2.x + g3.x;
        as1 += g0.y + g1.y + g2.y + g3.y;
    }
    for (; j < end; j++) {
        int sid = g_csr[j];
        float2 f = __half22float2(hs[sid * 64 + lane]);
        float2 g2v = __half22float2(hs[sid * 64 + 32 + lane]);
        ax0 += f.x; ax1 += f.y;
        as0 += g2v.x; as1 += g2v.y;
    }
    float dv = g_dinv[di];
    ((float2*)g_aggx)[di * 32 + lane] = make_float2(ax0, ax1);
    ((float2*)g_aggs)[di * 32 + lane] = make_float2(dv * as0, dv * as1);
}

// ---------------------------------------------------------------
// FAST TAIL (pooled-only): one pass over aggx/aggs.
__global__ void k_tail(const float* __restrict__ bg, int n, int G) {
    __shared__ float la_s[128 * 64];   // 32KB
    int tid = threadIdx.x;
    int c = tid & 63, q = tid >> 6;
    int r0 = blockIdx.x * 128;
    float bgc = bg[c];
    float accL = 0.f, accT = 0.f, cntRun = 0.f;
    int curg = -1;
    for (int rr = q; rr < 128; rr += 4) {
        int r = r0 + rr;
        if (r < n) {
            float v = g_aggx[r * 64 + c];
            float la = v > 0.f ? v : 0.01f * v;
            la_s[rr * 64 + c] = la;
            float tv = tanhf(g_aggs[r * 64 + c] + bgc);
            int g = g_batch[r];
            if ((unsigned)g >= (unsigned)G) g = 0;
            if (g != curg) {
                if (curg >= 0) {
                    atomicAdd(&g_Sla[curg * 64 + c], accL);
                    atomicAdd(&g_St[curg * 64 + c], accT);
                    if (c == 0) atomicAdd(&g_cntf[curg], cntRun);
                }
                curg = g; accL = 0.f; accT = 0.f; cntRun = 0.f;
            }
            accL += la; accT += tv; cntRun += 1.f;
        } else {
            la_s[rr * 64 + c] = 0.f;
        }
    }
    if (curg >= 0) {
        atomicAdd(&g_Sla[curg * 64 + c], accL);
        atomicAdd(&g_St[curg * 64 + c], accT);
        if (c == 0) atomicAdd(&g_cntf[curg], cntRun);
    }
    __syncthreads();
    // covariance: thread computes a 4x4 tile of C
    int a0 = (tid >> 4) * 4, b0 = (tid & 15) * 4;
    float C00=0,C01=0,C02=0,C03=0, C10=0,C11=0,C12=0,C13=0;
    float C20=0,C21=0,C22=0,C23=0, C30=0,C31=0,C32=0,C33=0;
    for (int r = 0; r < 128; r++) {
        float4 va = *(const float4*)&la_s[r * 64 + a0];
        float4 vb = *(const float4*)&la_s[r * 64 + b0];
        C00 += va.x*vb.x; C01 += va.x*vb.y; C02 += va.x*vb.z; C03 += va.x*vb.w;
        C10 += va.y*vb.x; C11 += va.y*vb.y; C12 += va.y*vb.z; C13 += va.y*vb.w;
        C20 += va.z*vb.x; C21 += va.z*vb.y; C22 += va.z*vb.z; C23 += va.z*vb.w;
        C30 += va.w*vb.x; C31 += va.w*vb.y; C32 += va.w*vb.z; C33 += va.w*vb.w;
    }
    atomicAdd(&g_C[(a0+0)*64+b0+0], C00); atomicAdd(&g_C[(a0+0)*64+b0+1], C01);
    atomicAdd(&g_C[(a0+0)*64+b0+2], C02); atomicAdd(&g_C[(a0+0)*64+b0+3], C03);
    atomicAdd(&g_C[(a0+1)*64+b0+0], C10); atomicAdd(&g_C[(a0+1)*64+b0+1], C11);
    atomicAdd(&g_C[(a0+1)*64+b0+2], C12); atomicAdd(&g_C[(a0+1)*64+b0+3], C13);
    atomicAdd(&g_C[(a0+2)*64+b0+0], C20); atomicAdd(&g_C[(a0+2)*64+b0+1], C21);
    atomicAdd(&g_C[(a0+2)*64+b0+2], C22); atomicAdd(&g_C[(a0+2)*64+b0+3], C23);
    atomicAdd(&g_C[(a0+3)*64+b0+0], C30); atomicAdd(&g_C[(a0+3)*64+b0+1], C31);
    atomicAdd(&g_C[(a0+3)*64+b0+2], C32); atomicAdd(&g_C[(a0+3)*64+b0+3], C33);
}

// BN stats from covariance
__global__ void k_bn2(const float* __restrict__ W2, int n, int G) {
    __shared__ float Cs[4096];
    __shared__ float W2s[4096];
    __shared__ float qpart[256];
    __shared__ float Tla[64];
    int tid = threadIdx.x;
    for (int i = tid; i < 4096; i += 256) { Cs[i] = g_C[i]; W2s[i] = W2[i]; }
    __syncthreads();
    int c = tid & 63, p = tid >> 6;
    float part = 0.f;
    for (int r = p; r < 64; r += 4) {
        float inner = 0.f;
#pragma unroll 16
        for (int k = 0; k < 64; k++) inner = fmaf(Cs[r * 64 + k], W2s[k * 64 + c], inner);
        part = fmaf(W2s[r * 64 + c], inner, part);
    }
    qpart[tid] = part;
    if (tid < 64) {
        float t = 0.f;
        for (int g = 0; g < G; g++) t += g_Sla[g * 64 + tid];
        Tla[tid] = t;
    }
    __syncthreads();
    if (tid < 64) {
        float quad = qpart[tid] + qpart[64 + tid] + qpart[128 + tid] + qpart[192 + tid];
        float mean = 0.f;
#pragma unroll 16
        for (int k = 0; k < 64; k++) mean = fmaf(Tla[k], W2s[k * 64 + tid], mean);
        mean /= (float)n;
        float var = quad / (float)n - mean * mean;
        g_stats[tid] = mean;
        g_stats[64 + tid] = rsqrtf(var + 1e-4f);
    }
}

__global__ void k_pool(const float* __restrict__ W2, const float* __restrict__ gamma,
                       const float* __restrict__ beta, const float* __restrict__ Wh,
                       const float* __restrict__ bh, float* __restrict__ pooled) {
    __shared__ float Sl[64], Stm[64], xls[64];
    int g = blockIdx.x;
    int c = threadIdx.x;
    Sl[c] = g_Sla[g * 64 + c];
    Stm[c] = g_St[g * 64 + c];
    float cnt = g_cntf[g];
    __syncthreads();
    float sx3 = 0.f;
#pragma unroll 16
    for (int k = 0; k < 64; k++) sx3 = fmaf(Sl[k], W2[k * 64 + c], sx3);
    float m = g_stats[c], iv = g_stats[64 + c];
    xls[c] = gamma[c] * iv * (sx3 - cnt * m) + cnt * beta[c];
    __syncthreads();
    float o = cnt * bh[c];
#pragma unroll 16
    for (int k = 0; k < 64; k++) o = fmaf(xls[k], Wh[k * 64 + c], o);
#pragma unroll 16
    for (int k = 0; k < 64; k++) o = fmaf(Stm[k], Wh[(64 + k) * 64 + c], o);
    pooled[g * 64 + c] = o;
}

// ---------------------------------------------------------------
// FALLBACK PATH (x_local output required)
__global__ void k3_mlp(const float* __restrict__ W2, const float* __restrict__ bg, int n) {
    __shared__ float Ws[64 * 64];
    __shared__ float shst[128];
    int tid = threadIdx.x;
    for (int i = tid; i < 64 * 64; i += 256) Ws[i] = W2[i];
    if (tid < 128) shst[tid] = 0.f;
    __syncthreads();
    int lane = tid & 31;
    int warp = blockIdx.x * 8 + (tid >> 5);
    int r0 = warp * 4;
    bool active = (r0 < n);
    float sum0 = 0.f, sum1 = 0.f, sq0 = 0.f, sq1 = 0.f;
    if (active) {
        float a0[4], a1[4];
#pragma unroll
        for (int r = 0; r < 4; r++) {
            int row = min(r0 + r, n - 1);
            float v0 = g_aggx[row * 64 + lane], v1 = g_aggx[row * 64 + 32 + lane];
            a0[r] = v0 > 0.f ? v0 : 0.01f * v0;
            a1[r] = v1 > 0.f ? v1 : 0.01f * v1;
        }
        float o0[4] = {0,0,0,0}, o1[4] = {0,0,0,0};
#pragma unroll 8
        for (int k = 0; k < 32; k++) {
            float w = Ws[k * 64 + lane], w2 = Ws[k * 64 + 32 + lane];
#pragma unroll
            for (int r = 0; r < 4; r++) {
                float xv = __shfl_sync(FULL, a0[r], k);
                o0[r] += xv * w; o1[r] += xv * w2;
            }
        }
#pragma unroll 8
        for (int k = 0; k < 32; k++) {
            int kk = k + 32;
            float w = Ws[kk * 64 + lane], w2 = Ws[kk * 64 + 32 + lane];
#pragma unroll
            for (int r = 0; r < 4; r++) {
                float xv = __shfl_sync(FULL, a1[r], k);
                o0[r] += xv * w; o1[r] += xv * w2;
            }
        }
        float b0 = bg[lane], b1 = bg[32 + lane];
#pragma unroll
        for (int r = 0; r < 4; r++) {
            int row = r0 + r;
            if (row >= n) break;
            g_x[row * 64 + lane] = o0[r]; g_x[row * 64 + 32 + lane] = o1[r];
            g_s[row * 64 + lane]      = tanhf(g_aggs[row * 64 + lane] + b0);
            g_s[row * 64 + 32 + lane] = tanhf(g_aggs[row * 64 + 32 + lane] + b1);
            sum0 += o0[r]; sq0 += o0[r] * o0[r];
            sum1 += o1[r]; sq1 += o1[r] * o1[r];
        }
    }
    atomicAdd(&shst[lane], sum0);
    atomicAdd(&shst[32 + lane], sum1);
    atomicAdd(&shst[64 + lane], sq0);
    atomicAdd(&shst[96 + lane], sq1);
    __syncthreads();
    if (tid < 128) atomicAdd(&g_stats[tid], shst[tid]);
}

__global__ void k_bn(int n) {
    int c = threadIdx.x;
    float mean = g_stats[c] / (float)n;
    float var = g_stats[64 + c] / (float)n - mean * mean;
    g_stats[c] = mean;
    g_stats[64 + c] = rsqrtf(var + 1e-4f);
}

__global__ void k_final(const float* __restrict__ gamma, const float* __restrict__ beta,
                        const float* __restrict__ Wh, const float* __restrict__ bh,
                        float* __restrict__ pooled, float* __restrict__ xl_out,
                        int n, int G) {
    __shared__ float Ws[128 * 64];
    int tid = threadIdx.x;
    for (int i = tid; i < 128 * 64; i += 256) Ws[i] = Wh[i];
    __syncthreads();
    int lane = tid & 31;
    int warp = blockIdx.x * 8 + (tid >> 5);
    int r0 = warp * 4;
    if (r0 >= n) return;
    float m0 = g_stats[lane],      m1 = g_stats[32 + lane];
    float i0 = g_stats[64 + lane], i1 = g_stats[96 + lane];
    float ga0 = gamma[lane], ga1 = gamma[32 + lane];
    float be0 = beta[lane],  be1 = beta[32 + lane];
    float xl0[4], xl1[4], sv0[4], sv1[4];
    int bidx[4];
#pragma unroll
    for (int r = 0; r < 4; r++) {
        int row = min(r0 + r, n - 1);
        xl0[r] = ga0 * (g_x[row * 64 + lane] - m0) * i0 + be0;
        xl1[r] = ga1 * (g_x[row * 64 + 32 + lane] - m1) * i1 + be1;
        sv0[r] = g_s[row * 64 + lane];
        sv1[r] = g_s[row * 64 + 32 + lane];
        int b = g_batch[row];
        bidx[r] = ((unsigned)b < (unsigned)G) ? b : 0;
    }
    float bh0 = bh[lane], bh1 = bh[32 + lane];
    float o0[4], o1[4];
#pragma unroll
    for (int r = 0; r < 4; r++) { o0[r] = bh0; o1[r] = bh1; }
#pragma unroll 8
    for (int k = 0; k < 32; k++) {
        float w = Ws[k * 64 + lane], w2 = Ws[k * 64 + 32 + lane];
#pragma unroll
        for (int r = 0; r < 4; r++) { float v = __shfl_sync(FULL, xl0[r], k); o0[r] += v * w; o1[r] += v * w2; }
    }
#pragma unroll 8
    for (int k = 0; k < 32; k++) {
        int kk = 32 + k;
        float w = Ws[kk * 64 + lane], w2 = Ws[kk * 64 + 32 + lane];
#pragma unroll
        for (int r = 0; r < 4; r++) { float v = __shfl_sync(FULL, xl1[r], k); o0[r] += v * w; o1[r] += v * w2; }
    }
#pragma unroll 8
    for (int k = 0; k < 32; k++) {
        int kk = 64 + k;
        float w = Ws[kk * 64 + lane], w2 = Ws[kk * 64 + 32 + lane];
#pragma unroll
        for (int r = 0; r < 4; r++) { float v = __shfl_sync(FULL, sv0[r], k); o0[r] += v * w; o1[r] += v * w2; }
    }
#pragma unroll 8
    for (int k = 0; k < 32; k++) {
        int kk = 96 + k;
        float w = Ws[kk * 64 + lane], w2 = Ws[kk * 64 + 32 + lane];
#pragma unroll
        for (int r = 0; r < 4; r++) { float v = __shfl_sync(FULL, sv1[r], k); o0[r] += v * w; o1[r] += v * w2; }
    }
    if (xl_out) {
#pragma unroll
        for (int r = 0; r < 4; r++) {
            int row = r0 + r;
            if (row >= n) break;
            xl_out[row * 64 + lane] = xl0[r];
            xl_out[row * 64 + 32 + lane] = xl1[r];
        }
    }
    int nvalid = min(n - r0, 4);
    for (int r = 0; r < nvalid; r++) {
        atomicAdd(&pooled[bidx[r] * 64 + lane], o0[r]);
        atomicAdd(&pooled[bidx[r] * 64 + 32 + lane], o1[r]);
    }
}

// ---------------------------------------------------------------
extern "C" void kernel_launch(void* const* d_in, const int* in_sizes, int n_in,
                              void* d_out, int out_size) {
    int ix, is_, iW1, iW2, iGa, iBe, iWg, iBg, iWh, iBh, iEi, iBa;
    if (n_in >= 2 && in_sizes[0] == in_sizes[1]) {
        ix = 0; is_ = 1; iW1 = 2; iW2 = 3; iGa = 4; iBe = 5;
        iWg = 6; iBg = 7; iWh = 8; iBh = 9; iEi = 10; iBa = 11;
    } else {
        iW1 = 0; iW2 = 1; iWg = 2; iWh = 3; iBa = 4; iBe = 5;
        iBg = 6; iBh = 7; iEi = 8; iGa = 9; is_ = 10; ix = 11;
    }

    const float* x     = (const float*)d_in[ix];
    const float* s     = (const float*)d_in[is_];
    const float* W1    = (const float*)d_in[iW1];
    const float* W2    = (const float*)d_in[iW2];
    const float* gamma = (const float*)d_in[iGa];
    const float* beta  = (const float*)d_in[iBe];
    const float* Wg    = (const float*)d_in[iWg];
    const float* bg    = (const float*)d_in[iBg];
    const float* Wh    = (const float*)d_in[iWh];
    const float* bh    = (const float*)d_in[iBh];
    const int* eraw    = (const int*)d_in[iEi];
    const int* braw    = (const int*)d_in[iBa];
    float* out = (float*)d_out;

    int n = in_sizes[ix] / 64;
    int E = in_sizes[iEi] / 2;
    if (n > MAXN) n = MAXN;
    if (E > MAXE) E = MAXE;

    // ---- output layout resolution ----
    float* pooledPtr;
    float* xlocalPtr;
    int G;
    float* gpool;
    cudaGetSymbolAddress((void**)&gpool, g_pooled);
    if (out_size > n * 64) {
        G = out_size / 64 - n;
        pooledPtr = out;
        xlocalPtr = out + (long)G * 64;
    } else if (out_size == n * 64) {
        G = 64;
        pooledPtr = gpool;
        xlocalPtr = out;
    } else {
        G = out_size / 64;
        pooledPtr = out;
        xlocalPtr = nullptr;
    }
    if (G > MAXG) G = MAXG;
    if (G < 1) G = 1;

    int gemmBlocks = (((n + 3) / 4) + 7) / 8;
    int nodeBlocks = (n + 7) / 8;
    int cvtBlocks = ((E > n ? E : n) + 255) / 256;
    int scanBlocks = (n + SCAN_ELEMS - 1) / SCAN_ELEMS;
    float* d_M;
    cudaGetSymbolAddress((void**)&d_M, g_M);

    // setup
    k_detect<<<1, 256>>>(eraw, 2 * E);
    k_zero<<<(n + 255) / 256, 256>>>(pooledPtr, n, G);
    k_convert<<<cvtBlocks, 256>>>(eraw, braw, E, n);
    k_scan1<<<scanBlocks, SCAN_BLOCK>>>(n);
    k_scan2<<<1, 64>>>(scanBlocks, n);
    k_scan3<<<scanBlocks, SCAN_BLOCK>>>(n);
    k_fill<<<(E + 255) / 256, 256>>>(E);
    k_precompute<<<128, 64>>>(W1, W2);

    // layer 0
    k1_gemm<<<gemmBlocks, 256>>>(x, s, W1, Wg, n);
    k_gather<<<nodeBlocks, 256>>>(n);
    // layer 1 (fused with layer-0 MLP second linear)
    k1_fused<<<gemmBlocks, 256>>>(d_M, W1 + 1 * 128 * 64 + 64 * 64, Wg + 1 * 64 * 64, bg, n);
    k_gather<<<nodeBlocks, 256>>>(n);
    // layer 2
    k1_fused<<<gemmBlocks, 256>>>(d_M + 4096, W1 + 2 * 128 * 64 + 64 * 64, Wg + 2 * 64 * 64, bg + 64, n);
    k_gather<<<nodeBlocks, 256>>>(n);

    if (xlocalPtr == nullptr) {
        // FAST TAIL: pooled-only, x3/s never materialized
        k_tail<<<(n + 127) / 128, 256>>>(bg + 2 * 64, n, G);
        k_bn2<<<1, 256>>>(W2 + 2 * 64 * 64, n, G);
        k_pool<<<G, 64>>>(W2 + 2 * 64 * 64, gamma + 2 * 64, beta + 2 * 64, Wh, bh, pooledPtr);
    } else {
        // fallback: x_local required
        k3_mlp<<<gemmBlocks, 256>>>(W2 + 2 * 64 * 64, bg + 2 * 64, n);
        k_bn<<<1, 64>>>(n);
        k_final<<<gemmBlocks, 256>>>(gamma + 2 * 64, beta + 2 * 64, Wh, bh,
                                     pooledPtr, xlocalPtr, n, G);
    }
}